// round 4
// baseline (speedup 1.0000x reference)
#include <cuda_runtime.h>
#include <cuda_bf16.h>
#include <math.h>
#include <stdint.h>

// ---------------------------------------------------------------------------
// Problem constants
// ---------------------------------------------------------------------------
#define BATCH   4
#define SEQ     2048
#define DMODEL  1024
#define NHEAD   16
#define DK      64
#define DFF     4096
#define NTOK    (BATCH * SEQ)          // 8192
#define LN_EPS  1e-5f

// ---------------------------------------------------------------------------
// Scratch (device globals — allocation-free rule)
// ---------------------------------------------------------------------------
__device__ float g_q   [NTOK * DMODEL];
__device__ float g_k   [NTOK * DMODEL];
__device__ float g_v   [NTOK * DMODEL];
__device__ float g_ctx [NTOK * DMODEL];
__device__ float g_attn[NTOK * DMODEL];
__device__ float g_h   [NTOK * DMODEL];
__device__ float g_hr  [NTOK * DMODEL];
__device__ float g_ff  [NTOK * DFF];
__device__ float g_f2  [NTOK * DMODEL];
// tf32-pre-rounded operands
__device__ float g_xr  [NTOK * DMODEL];
__device__ float g_wqr [DMODEL * DMODEL];
__device__ float g_wkr [DMODEL * DMODEL];
__device__ float g_wvr [DMODEL * DMODEL];
__device__ float g_wor [DMODEL * DMODEL];
__device__ float g_w1r [DMODEL * DFF];
__device__ float g_w2r [DFF * DMODEL];

// ---------------------------------------------------------------------------
// TF32 / async-copy helpers
// ---------------------------------------------------------------------------
__device__ __forceinline__ float to_tf32(float x) {
    asm("cvt.rna.tf32.f32 %0, %1;" : "=f"(x) : "f"(x));
    return x;
}

__device__ __forceinline__ uint32_t smem_u32(const void* p) {
    return (uint32_t)__cvta_generic_to_shared(p);
}
__device__ __forceinline__ void cp_async16(uint32_t dst, const void* src) {
    asm volatile("cp.async.cg.shared.global [%0], [%1], 16;\n" :: "r"(dst), "l"(src));
}
__device__ __forceinline__ void cp_commit() { asm volatile("cp.async.commit_group;\n"); }
__device__ __forceinline__ void cp_wait2()  { asm volatile("cp.async.wait_group 2;\n"); }
__device__ __forceinline__ void cp_wait1()  { asm volatile("cp.async.wait_group 1;\n"); }
__device__ __forceinline__ void cp_wait0()  { asm volatile("cp.async.wait_group 0;\n"); }

// mma.m16n8k8 row.col f32 += tf32 * tf32
__device__ __forceinline__ void mma_tf32(float* c, const uint32_t* a, const uint32_t* b) {
    asm volatile(
        "mma.sync.aligned.m16n8k8.row.col.f32.tf32.tf32.f32 "
        "{%0,%1,%2,%3}, {%4,%5,%6,%7}, {%8,%9}, {%0,%1,%2,%3};"
        : "+f"(c[0]), "+f"(c[1]), "+f"(c[2]), "+f"(c[3])
        : "r"(a[0]), "r"(a[1]), "r"(a[2]), "r"(a[3]), "r"(b[0]), "r"(b[1]));
}

// ---------------------------------------------------------------------------
// Elementwise tf32 rounding pass (inputs are multiples of 4 elements)
// ---------------------------------------------------------------------------
__global__ __launch_bounds__(256)
void round_tf32_kernel(const float* __restrict__ in, float* __restrict__ out, int n4) {
    int i = blockIdx.x * blockDim.x + threadIdx.x;
    if (i < n4) {
        float4 v = *(const float4*)(in + 4 * i);
        v.x = to_tf32(v.x); v.y = to_tf32(v.y);
        v.z = to_tf32(v.z); v.w = to_tf32(v.w);
        *(float4*)(out + 4 * i) = v;
    }
}

// ---------------------------------------------------------------------------
// TF32 tensor-core GEMM with 3-stage cp.async pipeline.
// C[M,N] = A[M,K] @ B[K,N] (+bias) (+relu) (+tf32-round on store). Row-major.
// A and B must be tf32-pre-rounded. 128x128 tile, BK=32, 256 threads (8 warps).
// Dynamic smem: 3 * (128*36 + 32*136) * 4 = 107,520 B -> 2 CTA/SM.
// ---------------------------------------------------------------------------
#define GA_LD 36
#define GB_LD 136
#define GEMM_STAGE_W (128 * GA_LD + 32 * GB_LD)
#define GEMM_SMEM (3 * GEMM_STAGE_W * (int)sizeof(float))

template<bool BIAS, bool RELU, bool CVT>
__global__ __launch_bounds__(256, 2)
void tf32_gemm(const float* __restrict__ A, const float* __restrict__ B,
               const float* __restrict__ bias, float* __restrict__ C,
               int M, int N, int K) {
    constexpr int BM = 128, BN = 128, BK = 32;
    extern __shared__ float gsm[];

    const int tid  = threadIdx.x;
    const int lane = tid & 31;
    const int warp = tid >> 5;
    const int wm   = warp & 1;
    const int wn   = warp >> 1;
    const int g    = lane >> 2;
    const int th   = lane & 3;

    const int rowBase = blockIdx.y * BM;
    const int colBase = blockIdx.x * BN;

    const int arow = tid >> 3;          // 0..31
    const int acol = (tid & 7) * 4;     // 0..28
    const int brow = tid >> 5;          // 0..7
    const int bcol = (tid & 31) * 4;    // 0..124

    float acc[4][4][4];
#pragma unroll
    for (int i = 0; i < 4; i++)
#pragma unroll
        for (int j = 0; j < 4; j++)
#pragma unroll
            for (int r = 0; r < 4; r++) acc[i][j][r] = 0.f;

    auto As = [&](int s) -> float* { return gsm + s * GEMM_STAGE_W; };
    auto Bs = [&](int s) -> float* { return gsm + s * GEMM_STAGE_W + BM * GA_LD; };

    auto load_tile = [&](int kt, int s) {
        float* as = As(s);
        float* bs = Bs(s);
#pragma unroll
        for (int p = 0; p < 4; p++) {
            int r = arow + p * 32;
            cp_async16(smem_u32(as + r * GA_LD + acol),
                       A + (size_t)(rowBase + r) * K + kt + acol);
        }
#pragma unroll
        for (int p = 0; p < 4; p++) {
            int r = brow + p * 8;
            cp_async16(smem_u32(bs + r * GB_LD + bcol),
                       B + (size_t)(kt + r) * N + colBase + bcol);
        }
    };

    const int nk = K / BK;
    load_tile(0, 0);       cp_commit();
    load_tile(BK, 1);      cp_commit();

    for (int it = 0; it < nk; it++) {
        const int s = it % 3;
        if (it + 2 < nk) {
            load_tile((it + 2) * BK, (it + 2) % 3);
            cp_commit();
            cp_wait2();
        } else if (it + 1 < nk) {
            cp_wait1();
        } else {
            cp_wait0();
        }
        __syncthreads();

        const float* as = As(s);
        const float* bs = Bs(s);
#pragma unroll
        for (int ks = 0; ks < 4; ks++) {
            const int k0 = ks * 8;
            uint32_t af[4][4], bf[4][2];
#pragma unroll
            for (int mt = 0; mt < 4; mt++) {
                int r0 = wm * 64 + mt * 16 + g;
                af[mt][0] = __float_as_uint(as[(r0    ) * GA_LD + k0 + th    ]);
                af[mt][1] = __float_as_uint(as[(r0 + 8) * GA_LD + k0 + th    ]);
                af[mt][2] = __float_as_uint(as[(r0    ) * GA_LD + k0 + th + 4]);
                af[mt][3] = __float_as_uint(as[(r0 + 8) * GA_LD + k0 + th + 4]);
            }
#pragma unroll
            for (int nt = 0; nt < 4; nt++) {
                int c0 = wn * 32 + nt * 8 + g;
                bf[nt][0] = __float_as_uint(bs[(k0 + th    ) * GB_LD + c0]);
                bf[nt][1] = __float_as_uint(bs[(k0 + th + 4) * GB_LD + c0]);
            }
#pragma unroll
            for (int mt = 0; mt < 4; mt++)
#pragma unroll
                for (int nt = 0; nt < 4; nt++)
                    mma_tf32(acc[mt][nt], af[mt], bf[nt]);
        }
        __syncthreads();
    }

    // epilogue
#pragma unroll
    for (int mt = 0; mt < 4; mt++) {
        const int r0 = rowBase + wm * 64 + mt * 16 + g;
#pragma unroll
        for (int nt = 0; nt < 4; nt++) {
            const int c0 = colBase + wn * 32 + nt * 8 + 2 * th;
            float2 v0 = make_float2(acc[mt][nt][0], acc[mt][nt][1]);
            float2 v1 = make_float2(acc[mt][nt][2], acc[mt][nt][3]);
            if (BIAS) {
                float2 bb = *(const float2*)(bias + c0);
                v0.x += bb.x; v0.y += bb.y;
                v1.x += bb.x; v1.y += bb.y;
            }
            if (RELU) {
                v0.x = fmaxf(v0.x, 0.f); v0.y = fmaxf(v0.y, 0.f);
                v1.x = fmaxf(v1.x, 0.f); v1.y = fmaxf(v1.y, 0.f);
            }
            if (CVT) {
                v0.x = to_tf32(v0.x); v0.y = to_tf32(v0.y);
                v1.x = to_tf32(v1.x); v1.y = to_tf32(v1.y);
            }
            *(float2*)(C + (size_t)r0 * N + c0)       = v0;
            *(float2*)(C + (size_t)(r0 + 8) * N + c0) = v1;
        }
    }
}

// ---------------------------------------------------------------------------
// Flash attention, TF32 tensor cores, vectorized fragment loads.
// grid = (SEQ/64, NHEAD, BATCH), 128 threads (4 warps), 16 q-rows per warp.
// smem tiles, each [64][68] floats:
//   Ks: row = kv index, cols = pair-permuted d     (B-frag = one LDS.64)
//   Vt: row = d index,  cols = pair-permuted kv    (B-frag = one LDS.64)
//   Ps: row = q index,  cols = pair-permuted kv    (A-frag = two LDS.64)
// Pair-perm within each 8-block: slot(w) = (w&3)*2 + (w>>2), so (w, w+4)
// land adjacent. Inputs q/k/v are tf32-pre-rounded; no cvt on loads.
// smem: 3 * 64*68*4 = 52,224 B -> 4 CTA/SM.
// ---------------------------------------------------------------------------
#define AT_LD   68
#define AT_TILE (64 * AT_LD)
#define AT_SMEM (3 * AT_TILE * (int)sizeof(float))

__device__ __forceinline__ int pslot(int w) { return ((w & 3) << 1) | (w >> 2); }

__global__ __launch_bounds__(128, 4)
void flash_attn_tf32(const float* __restrict__ q, const float* __restrict__ k,
                     const float* __restrict__ v, float* __restrict__ ctx) {
    extern __shared__ float sm[];
    float* Ks = sm;
    float* Vt = Ks + AT_TILE;
    float* Ps = Vt + AT_TILE;   // also stages Q (unpermuted) once at start

    const int tid  = threadIdx.x;
    const int lane = tid & 31;
    const int warp = tid >> 5;        // 0..3 -> 16 q rows each
    const int g    = lane >> 2;
    const int th   = lane & 3;
    const int qt   = blockIdx.x;
    const int h    = blockIdx.y;
    const int b    = blockIdx.z;

    const size_t base = (size_t)b * SEQ * DMODEL + (size_t)h * DK;
    const float scale = 0.125f;       // 1/sqrt(64)
    const int qrow = warp * 16 + g;   // this thread's row pair: qrow, qrow+8
    const int sA = pslot(2 * th);     // permuted slot of col 2*th within 8-block
    const int sB = pslot(2 * th + 1);

    // ---- stage Q tile once (unpermuted), pull fragments into registers ----
    for (int e = tid; e < 64 * 64; e += 128) {
        int r = e >> 6, d = e & 63;
        Ps[r * AT_LD + d] = q[base + (size_t)(qt * 64 + r) * DMODEL + d];
    }
    __syncthreads();

    uint32_t qf[8][4];
#pragma unroll
    for (int ks = 0; ks < 8; ks++) {
        const int k0 = ks * 8;
        qf[ks][0] = __float_as_uint(Ps[qrow * AT_LD + k0 + th]);
        qf[ks][1] = __float_as_uint(Ps[(qrow + 8) * AT_LD + k0 + th]);
        qf[ks][2] = __float_as_uint(Ps[qrow * AT_LD + k0 + th + 4]);
        qf[ks][3] = __float_as_uint(Ps[(qrow + 8) * AT_LD + k0 + th + 4]);
    }
    __syncthreads();

    float m0 = -1e30f, m1 = -1e30f, l0 = 0.f, l1 = 0.f;
    float o[8][4];
#pragma unroll
    for (int i = 0; i < 8; i++)
#pragma unroll
        for (int j = 0; j < 4; j++) o[i][j] = 0.f;

    for (int kt = 0; kt < SEQ / 64; kt++) {
        // load K (pair-permuted d) and V (transposed, pair-permuted kv)
        for (int e = tid; e < 64 * 64; e += 128) {
            int r = e >> 6, d = e & 63;
            size_t go = base + (size_t)(kt * 64 + r) * DMODEL + d;
            int pd = (d & ~7) | pslot(d & 7);
            int pr = (r & ~7) | pslot(r & 7);
            Ks[r * AT_LD + pd] = k[go];
            Vt[d * AT_LD + pr] = v[go];
        }
        __syncthreads();

        // ---- scores S = Q @ K^T : M=16, N=64 (kv), K=64 (d) ----
        float s[8][4];
#pragma unroll
        for (int nt = 0; nt < 8; nt++)
#pragma unroll
            for (int r = 0; r < 4; r++) s[nt][r] = 0.f;

#pragma unroll
        for (int ks = 0; ks < 8; ks++) {
            const int k0 = ks * 8;
#pragma unroll
            for (int nt = 0; nt < 8; nt++) {
                float2 kk = *(const float2*)&Ks[(nt * 8 + g) * AT_LD + k0 + 2 * th];
                uint32_t bf[2];
                bf[0] = __float_as_uint(kk.x);   // d = k0+th
                bf[1] = __float_as_uint(kk.y);   // d = k0+th+4
                mma_tf32(s[nt], qf[ks], bf);
            }
        }

        // ---- online softmax (rows qrow, qrow+8) ----
        float rm0 = -1e30f, rm1 = -1e30f;
#pragma unroll
        for (int nt = 0; nt < 8; nt++) {
            s[nt][0] *= scale; s[nt][1] *= scale;
            s[nt][2] *= scale; s[nt][3] *= scale;
            rm0 = fmaxf(rm0, fmaxf(s[nt][0], s[nt][1]));
            rm1 = fmaxf(rm1, fmaxf(s[nt][2], s[nt][3]));
        }
        rm0 = fmaxf(rm0, __shfl_xor_sync(0xffffffffu, rm0, 1));
        rm0 = fmaxf(rm0, __shfl_xor_sync(0xffffffffu, rm0, 2));
        rm1 = fmaxf(rm1, __shfl_xor_sync(0xffffffffu, rm1, 1));
        rm1 = fmaxf(rm1, __shfl_xor_sync(0xffffffffu, rm1, 2));

        const float mn0 = fmaxf(m0, rm0);
        const float mn1 = fmaxf(m1, rm1);
        const float corr0 = __expf(m0 - mn0);
        const float corr1 = __expf(m1 - mn1);

        float rs0 = 0.f, rs1 = 0.f;
#pragma unroll
        for (int nt = 0; nt < 8; nt++) {
            float p00 = __expf(s[nt][0] - mn0);
            float p01 = __expf(s[nt][1] - mn0);
            float p10 = __expf(s[nt][2] - mn1);
            float p11 = __expf(s[nt][3] - mn1);
            rs0 += p00 + p01;
            rs1 += p10 + p11;
            Ps[qrow * AT_LD + nt * 8 + sA]       = to_tf32(p00);
            Ps[qrow * AT_LD + nt * 8 + sB]       = to_tf32(p01);
            Ps[(qrow + 8) * AT_LD + nt * 8 + sA] = to_tf32(p10);
            Ps[(qrow + 8) * AT_LD + nt * 8 + sB] = to_tf32(p11);
        }
        rs0 += __shfl_xor_sync(0xffffffffu, rs0, 1);
        rs0 += __shfl_xor_sync(0xffffffffu, rs0, 2);
        rs1 += __shfl_xor_sync(0xffffffffu, rs1, 1);
        rs1 += __shfl_xor_sync(0xffffffffu, rs1, 2);

        l0 = l0 * corr0 + rs0;
        l1 = l1 * corr1 + rs1;
        m0 = mn0;
        m1 = mn1;

#pragma unroll
        for (int dt = 0; dt < 8; dt++) {
            o[dt][0] *= corr0; o[dt][1] *= corr0;
            o[dt][2] *= corr1; o[dt][3] *= corr1;
        }
        __syncwarp();   // Ps rows are warp-private

        // ---- O += P @ V : M=16, N=64 (d), K=64 (kv) ----
#pragma unroll
        for (int ks = 0; ks < 8; ks++) {
            const int k0 = ks * 8;
            float2 a02 = *(const float2*)&Ps[qrow * AT_LD + k0 + 2 * th];
            float2 a13 = *(const float2*)&Ps[(qrow + 8) * AT_LD + k0 + 2 * th];
            uint32_t af[4];
            af[0] = __float_as_uint(a02.x);   // row qrow,   kv k0+th
            af[1] = __float_as_uint(a13.x);   // row qrow+8, kv k0+th
            af[2] = __float_as_uint(a02.y);   // row qrow,   kv k0+th+4
            af[3] = __float_as_uint(a13.y);   // row qrow+8, kv k0+th+4
#pragma unroll
            for (int dt = 0; dt < 8; dt++) {
                float2 vv = *(const float2*)&Vt[(dt * 8 + g) * AT_LD + k0 + 2 * th];
                uint32_t bf[2];
                bf[0] = __float_as_uint(vv.x);   // V[k0+th][d]
                bf[1] = __float_as_uint(vv.y);   // V[k0+th+4][d]
                mma_tf32(o[dt], af, bf);
            }
        }
        __syncthreads();   // done with Ks/Vt/Ps before next tile
    }

    // epilogue (tf32-round: ctx feeds the Wo GEMM as an MMA operand)
    const float inv0 = 1.0f / l0;
    const float inv1 = 1.0f / l1;
    const size_t row0 = base + (size_t)(qt * 64 + qrow) * DMODEL;
    const size_t row1 = base + (size_t)(qt * 64 + qrow + 8) * DMODEL;
#pragma unroll
    for (int dt = 0; dt < 8; dt++) {
        const int c0 = dt * 8 + 2 * th;
        *(float2*)(ctx + row0 + c0) =
            make_float2(to_tf32(o[dt][0] * inv0), to_tf32(o[dt][1] * inv0));
        *(float2*)(ctx + row1 + c0) =
            make_float2(to_tf32(o[dt][2] * inv1), to_tf32(o[dt][3] * inv1));
    }
}

// ---------------------------------------------------------------------------
// out = LayerNorm(a + b) * gamma + beta; optional second tf32-rounded copy.
// ---------------------------------------------------------------------------
__global__ __launch_bounds__(256)
void add_ln_kernel(const float* __restrict__ a, const float* __restrict__ b,
                   const float* __restrict__ gamma, const float* __restrict__ beta,
                   float* __restrict__ out, float* __restrict__ out_r) {
    const int row = blockIdx.x;
    const int tid = threadIdx.x;
    const size_t off = (size_t)row * DMODEL;

    __shared__ float r1[8], r2[8];

    float vals[4];
    float sum = 0.f, sq = 0.f;
#pragma unroll
    for (int t = 0; t < 4; t++) {
        int c = tid + t * 256;
        float vv = a[off + c] + b[off + c];
        vals[t] = vv;
        sum += vv;
        sq  += vv * vv;
    }
#pragma unroll
    for (int o = 16; o > 0; o >>= 1) {
        sum += __shfl_xor_sync(0xffffffffu, sum, o);
        sq  += __shfl_xor_sync(0xffffffffu, sq,  o);
    }
    const int wid = tid >> 5;
    if ((tid & 31) == 0) { r1[wid] = sum; r2[wid] = sq; }
    __syncthreads();
    float tot1 = 0.f, tot2 = 0.f;
#pragma unroll
    for (int w = 0; w < 8; w++) { tot1 += r1[w]; tot2 += r2[w]; }

    const float mu   = tot1 * (1.0f / DMODEL);
    const float var  = tot2 * (1.0f / DMODEL) - mu * mu;
    const float rstd = rsqrtf(var + LN_EPS);

#pragma unroll
    for (int t = 0; t < 4; t++) {
        int c = tid + t * 256;
        float y = (vals[t] - mu) * rstd * gamma[c] + beta[c];
        out[off + c] = y;
        if (out_r) out_r[off + c] = to_tf32(y);
    }
}

// ---------------------------------------------------------------------------
// Launcher
// ---------------------------------------------------------------------------
extern "C" void kernel_launch(void* const* d_in, const int* in_sizes, int n_in,
                              void* d_out, int out_size) {
    (void)in_sizes; (void)n_in; (void)out_size;
    const float* x   = (const float*)d_in[0];
    const float* wq  = (const float*)d_in[1];
    const float* wk  = (const float*)d_in[2];
    const float* wv  = (const float*)d_in[3];
    const float* wo  = (const float*)d_in[4];
    const float* w1  = (const float*)d_in[5];
    const float* b1  = (const float*)d_in[6];
    const float* w2  = (const float*)d_in[7];
    const float* b2  = (const float*)d_in[8];
    const float* g1  = (const float*)d_in[9];
    const float* be1 = (const float*)d_in[10];
    const float* g2  = (const float*)d_in[11];
    const float* be2 = (const float*)d_in[12];
    float* out = (float*)d_out;

    float *q, *k, *v, *ctx, *attn, *h, *hr, *ff, *f2;
    float *xr, *wqr, *wkr, *wvr, *wor, *w1r, *w2r;
    cudaGetSymbolAddress((void**)&q,    g_q);
    cudaGetSymbolAddress((void**)&k,    g_k);
    cudaGetSymbolAddress((void**)&v,    g_v);
    cudaGetSymbolAddress((void**)&ctx,  g_ctx);
    cudaGetSymbolAddress((void**)&attn, g_attn);
    cudaGetSymbolAddress((void**)&h,    g_h);
    cudaGetSymbolAddress((void**)&hr,   g_hr);
    cudaGetSymbolAddress((void**)&ff,   g_ff);
    cudaGetSymbolAddress((void**)&f2,   g_f2);
    cudaGetSymbolAddress((void**)&xr,   g_xr);
    cudaGetSymbolAddress((void**)&wqr,  g_wqr);
    cudaGetSymbolAddress((void**)&wkr,  g_wkr);
    cudaGetSymbolAddress((void**)&wvr,  g_wvr);
    cudaGetSymbolAddress((void**)&wor,  g_wor);
    cudaGetSymbolAddress((void**)&w1r,  g_w1r);
    cudaGetSymbolAddress((void**)&w2r,  g_w2r);

    cudaFuncSetAttribute(tf32_gemm<false, false, true>,
                         cudaFuncAttributeMaxDynamicSharedMemorySize, GEMM_SMEM);
    cudaFuncSetAttribute(tf32_gemm<false, false, false>,
                         cudaFuncAttributeMaxDynamicSharedMemorySize, GEMM_SMEM);
    cudaFuncSetAttribute(tf32_gemm<true, true, true>,
                         cudaFuncAttributeMaxDynamicSharedMemorySize, GEMM_SMEM);
    cudaFuncSetAttribute(tf32_gemm<true, false, false>,
                         cudaFuncAttributeMaxDynamicSharedMemorySize, GEMM_SMEM);
    cudaFuncSetAttribute(flash_attn_tf32,
                         cudaFuncAttributeMaxDynamicSharedMemorySize, AT_SMEM);

    // ---- pre-round MMA operands to tf32 (bit-exact vs per-load cvt) ----
    {
        const int n_x = NTOK * DMODEL / 4;
        const int n_w = DMODEL * DMODEL / 4;
        const int n_f = DMODEL * DFF / 4;
        round_tf32_kernel<<<(n_x + 255) / 256, 256>>>(x,  xr,  n_x);
        round_tf32_kernel<<<(n_w + 255) / 256, 256>>>(wq, wqr, n_w);
        round_tf32_kernel<<<(n_w + 255) / 256, 256>>>(wk, wkr, n_w);
        round_tf32_kernel<<<(n_w + 255) / 256, 256>>>(wv, wvr, n_w);
        round_tf32_kernel<<<(n_w + 255) / 256, 256>>>(wo, wor, n_w);
        round_tf32_kernel<<<(n_f + 255) / 256, 256>>>(w1, w1r, n_f);
        round_tf32_kernel<<<(n_f + 255) / 256, 256>>>(w2, w2r, n_f);
    }

    const dim3 g_dd(DMODEL / 128, NTOK / 128);   // (8, 64)
    const dim3 g_df(DFF / 128,    NTOK / 128);   // (32, 64)

    // Q, K, V projections (outputs rounded: feed attention MMAs)
    tf32_gemm<false, false, true><<<g_dd, 256, GEMM_SMEM>>>(xr, wqr, nullptr, q, NTOK, DMODEL, DMODEL);
    tf32_gemm<false, false, true><<<g_dd, 256, GEMM_SMEM>>>(xr, wkr, nullptr, k, NTOK, DMODEL, DMODEL);
    tf32_gemm<false, false, true><<<g_dd, 256, GEMM_SMEM>>>(xr, wvr, nullptr, v, NTOK, DMODEL, DMODEL);

    // attention (ctx rounded in epilogue: feeds Wo GEMM)
    flash_attn_tf32<<<dim3(SEQ / 64, NHEAD, BATCH), 128, AT_SMEM>>>(q, k, v, ctx);

    // output projection (feeds add_ln only: no rounding)
    tf32_gemm<false, false, false><<<g_dd, 256, GEMM_SMEM>>>(ctx, wor, nullptr, attn, NTOK, DMODEL, DMODEL);

    // add & norm 1 (h exact for residual, hr rounded for FFN1)
    add_ln_kernel<<<NTOK, 256>>>(x, attn, g1, be1, h, hr);

    // FFN (ff rounded: feeds FFN2; f2 feeds add_ln only)
    tf32_gemm<true, true,  true ><<<g_df, 256, GEMM_SMEM>>>(hr, w1r, b1, ff, NTOK, DFF,    DMODEL);
    tf32_gemm<true, false, false><<<g_dd, 256, GEMM_SMEM>>>(ff, w2r, b2, f2, NTOK, DMODEL, DFF);

    // add & norm 2
    add_ln_kernel<<<NTOK, 256>>>(h, f2, g2, be2, out, nullptr);
}

// round 6
// speedup vs baseline: 1.9254x; 1.9254x over previous
#include <cuda_runtime.h>
#include <cuda_fp16.h>
#include <math.h>
#include <stdint.h>

// ---------------------------------------------------------------------------
// Problem constants
// ---------------------------------------------------------------------------
#define BATCH   4
#define SEQ     2048
#define DMODEL  1024
#define NHEAD   16
#define DK      64
#define DFF     4096
#define NTOK    (BATCH * SEQ)          // 8192
#define LN_EPS  1e-5f

// ---------------------------------------------------------------------------
// Scratch (device globals — allocation-free rule)
// ---------------------------------------------------------------------------
__device__ __half g_xh  [NTOK * DMODEL];
__device__ __half g_qh  [NTOK * DMODEL];
__device__ __half g_kh  [NTOK * DMODEL];
__device__ __half g_vh  [NTOK * DMODEL];
__device__ __half g_ctxh[NTOK * DMODEL];
__device__ __half g_hrh [NTOK * DMODEL];
__device__ __half g_ffh [NTOK * DFF];
__device__ float  g_attn[NTOK * DMODEL];
__device__ float  g_h   [NTOK * DMODEL];
__device__ float  g_f2  [NTOK * DMODEL];
// fp16 K-major weights: wt[n][k] = (half)w[k][n]
__device__ __half g_wqt [DMODEL * DMODEL];
__device__ __half g_wkt [DMODEL * DMODEL];
__device__ __half g_wvt [DMODEL * DMODEL];
__device__ __half g_wot [DMODEL * DMODEL];
__device__ __half g_w1t [DFF * DMODEL];
__device__ __half g_w2t [DMODEL * DFF];

// ---------------------------------------------------------------------------
// Helpers
// ---------------------------------------------------------------------------
__device__ __forceinline__ uint32_t smem_u32(const void* p) {
    return (uint32_t)__cvta_generic_to_shared(p);
}
__device__ __forceinline__ void cp_async16(uint32_t dst, const void* src) {
    asm volatile("cp.async.cg.shared.global [%0], [%1], 16;\n" :: "r"(dst), "l"(src));
}
__device__ __forceinline__ void cp_commit() { asm volatile("cp.async.commit_group;\n"); }
__device__ __forceinline__ void cp_wait2()  { asm volatile("cp.async.wait_group 2;\n"); }
__device__ __forceinline__ void cp_wait1()  { asm volatile("cp.async.wait_group 1;\n"); }
__device__ __forceinline__ void cp_wait0()  { asm volatile("cp.async.wait_group 0;\n"); }

// mma.m16n8k16 row.col f32 += f16 * f16
__device__ __forceinline__ void mma_f16(float* c, const uint32_t* a, const uint32_t* b) {
    asm volatile(
        "mma.sync.aligned.m16n8k16.row.col.f32.f16.f16.f32 "
        "{%0,%1,%2,%3}, {%4,%5,%6,%7}, {%8,%9}, {%0,%1,%2,%3};"
        : "+f"(c[0]), "+f"(c[1]), "+f"(c[2]), "+f"(c[3])
        : "r"(a[0]), "r"(a[1]), "r"(a[2]), "r"(a[3]), "r"(b[0]), "r"(b[1]));
}

// ---------------------------------------------------------------------------
// Prep kernels: fp32 -> fp16 (optionally transposed)
// ---------------------------------------------------------------------------
__global__ __launch_bounds__(256)
void f2h_kernel(const float* __restrict__ in, __half* __restrict__ out, int n4) {
    int i = blockIdx.x * blockDim.x + threadIdx.x;
    if (i < n4) {
        float4 v = *(const float4*)(in + 4 * i);
        __half2 h01 = __floats2half2_rn(v.x, v.y);
        __half2 h23 = __floats2half2_rn(v.z, v.w);
        *(__half2*)(out + 4 * i)     = h01;
        *(__half2*)(out + 4 * i + 2) = h23;
    }
}

// wt[n][k] = half(w[k][n]); w is [K][N] row-major. block (32,8), tiles 32x32.
__global__ __launch_bounds__(256)
void transpose_f2h_kernel(const float* __restrict__ w, __half* __restrict__ wt,
                          int K, int N) {
    __shared__ float t[32][33];
    const int n0 = blockIdx.x * 32;
    const int k0 = blockIdx.y * 32;
#pragma unroll
    for (int i = threadIdx.y; i < 32; i += 8)
        t[i][threadIdx.x] = w[(size_t)(k0 + i) * N + n0 + threadIdx.x];
    __syncthreads();
#pragma unroll
    for (int i = threadIdx.y; i < 32; i += 8)
        wt[(size_t)(n0 + i) * K + k0 + threadIdx.x] = __float2half(t[threadIdx.x][i]);
}

// ---------------------------------------------------------------------------
// FP16 tensor-core GEMM, 3-stage cp.async pipeline.
// C[M,N] = A[M,K] @ BT[N,K]^T (+bias)(+relu). A, BT fp16 row-major (K-major).
// 128x128 tile, BK=64, 256 threads (8 warps), warp tile 64x32, m16n8k16.
// smem per stage: (128 + 128) rows x 72 halves = 36,864 B; 3 stages = 110,592 B.
// ---------------------------------------------------------------------------
#define HLD 72           // halves per smem row (64 + 8 pad): frag bank = 4g+th
#define HSTAGE_H (128 * HLD)          // halves per matrix per stage
#define HSTAGE_ALL (2 * HSTAGE_H)     // A + B halves per stage
#define HGEMM_SMEM (3 * HSTAGE_ALL * (int)sizeof(__half))

template<bool BIAS, bool RELU, bool HOUT>
__global__ __launch_bounds__(256, 2)
void hgemm(const __half* __restrict__ A, const __half* __restrict__ BT,
           const float* __restrict__ bias, void* __restrict__ Cv,
           int M, int N, int K) {
    extern __shared__ __half hsm[];

    const int tid  = threadIdx.x;
    const int lane = tid & 31;
    const int warp = tid >> 5;
    const int wm   = warp & 1;        // 64-row half
    const int wn   = warp >> 1;       // 32-col quarter
    const int g    = lane >> 2;       // 0..7
    const int th   = lane & 3;        // 0..3

    const int rowBase = blockIdx.y * 128;
    const int colBase = blockIdx.x * 128;

    float acc[4][4][4];
#pragma unroll
    for (int i = 0; i < 4; i++)
#pragma unroll
        for (int j = 0; j < 4; j++)
#pragma unroll
            for (int r = 0; r < 4; r++) acc[i][j][r] = 0.f;

    auto load_chunk = [&](int c) {
        const int s = c % 3;
        __half* as = hsm + s * HSTAGE_ALL;
        __half* bs = as + HSTAGE_H;
        const size_t koff = (size_t)c * 64;
#pragma unroll
        for (int p = 0; p < 4; p++) {
            int idx = tid + p * 256;            // 0..1023
            int r = idx >> 3, j = (idx & 7) * 8;
            cp_async16(smem_u32(as + r * HLD + j),
                       A  + (size_t)(rowBase + r) * K + koff + j);
            cp_async16(smem_u32(bs + r * HLD + j),
                       BT + (size_t)(colBase + r) * K + koff + j);
        }
        cp_commit();
    };

    const int nk = K / 64;
    load_chunk(0);
    load_chunk(1);

    for (int it = 0; it < nk; it++) {
        const int s = it % 3;
        if (it + 2 < nk) {
            load_chunk(it + 2);
            cp_wait2();
        } else if (it + 1 < nk) {
            cp_wait1();
        } else {
            cp_wait0();
        }
        __syncthreads();

        const __half* as = hsm + s * HSTAGE_ALL;
        const __half* bs = as + HSTAGE_H;
#pragma unroll
        for (int ks = 0; ks < 4; ks++) {
            const int k0 = ks * 16;
            uint32_t af[4][4], bf[4][2];
#pragma unroll
            for (int mt = 0; mt < 4; mt++) {
                int r0 = wm * 64 + mt * 16 + g;
                af[mt][0] = *(const uint32_t*)&as[(r0    ) * HLD + k0 + 2 * th    ];
                af[mt][1] = *(const uint32_t*)&as[(r0 + 8) * HLD + k0 + 2 * th    ];
                af[mt][2] = *(const uint32_t*)&as[(r0    ) * HLD + k0 + 2 * th + 8];
                af[mt][3] = *(const uint32_t*)&as[(r0 + 8) * HLD + k0 + 2 * th + 8];
            }
#pragma unroll
            for (int nt = 0; nt < 4; nt++) {
                int c0 = wn * 32 + nt * 8 + g;
                bf[nt][0] = *(const uint32_t*)&bs[c0 * HLD + k0 + 2 * th    ];
                bf[nt][1] = *(const uint32_t*)&bs[c0 * HLD + k0 + 2 * th + 8];
            }
#pragma unroll
            for (int mt = 0; mt < 4; mt++)
#pragma unroll
                for (int nt = 0; nt < 4; nt++)
                    mma_f16(acc[mt][nt], af[mt], bf[nt]);
        }
        __syncthreads();
    }

    // epilogue: c0,c1 -> row r0 cols (2th,2th+1); c2,c3 -> row r0+8
    float* Cf = (float*)Cv;
    __half* Ch = (__half*)Cv;
#pragma unroll
    for (int mt = 0; mt < 4; mt++) {
        const int r0 = rowBase + wm * 64 + mt * 16 + g;
#pragma unroll
        for (int nt = 0; nt < 4; nt++) {
            const int c0 = colBase + wn * 32 + nt * 8 + 2 * th;
            float2 v0 = make_float2(acc[mt][nt][0], acc[mt][nt][1]);
            float2 v1 = make_float2(acc[mt][nt][2], acc[mt][nt][3]);
            if (BIAS) {
                float2 bb = *(const float2*)(bias + c0);
                v0.x += bb.x; v0.y += bb.y;
                v1.x += bb.x; v1.y += bb.y;
            }
            if (RELU) {
                v0.x = fmaxf(v0.x, 0.f); v0.y = fmaxf(v0.y, 0.f);
                v1.x = fmaxf(v1.x, 0.f); v1.y = fmaxf(v1.y, 0.f);
            }
            if (HOUT) {
                *(__half2*)(Ch + (size_t)r0 * N + c0)       = __floats2half2_rn(v0.x, v0.y);
                *(__half2*)(Ch + (size_t)(r0 + 8) * N + c0) = __floats2half2_rn(v1.x, v1.y);
            } else {
                *(float2*)(Cf + (size_t)r0 * N + c0)       = v0;
                *(float2*)(Cf + (size_t)(r0 + 8) * N + c0) = v1;
            }
        }
    }
}

// ---------------------------------------------------------------------------
// Flash attention, FP16 m16n8k16 tensor cores.
// grid = (SEQ/64, NHEAD, BATCH), 128 threads (4 warps), 16 q-rows per warp.
// smem (halves, LD=72): Ks [kv][d], Vt [d][kv], Ps [q][kv] (stages Q first).
// All fragment loads are single 32-bit LDS (natural k-pair adjacency in fp16).
// smem: 3 * 64*72*2 = 27,648 B.
// ---------------------------------------------------------------------------
#define ALD   72
#define ATILE (64 * ALD)
#define AT_SMEM (3 * ATILE * (int)sizeof(__half))

__global__ __launch_bounds__(128, 4)
void flash_attn_h(const __half* __restrict__ q, const __half* __restrict__ k,
                  const __half* __restrict__ v, __half* __restrict__ ctx) {
    extern __shared__ __half asm_[];
    __half* Ks = asm_;
    __half* Vt = Ks + ATILE;
    __half* Ps = Vt + ATILE;

    const int tid  = threadIdx.x;
    const int lane = tid & 31;
    const int warp = tid >> 5;
    const int g    = lane >> 2;
    const int th   = lane & 3;
    const int qt   = blockIdx.x;
    const int h    = blockIdx.y;
    const int b    = blockIdx.z;

    const size_t base = (size_t)b * SEQ * DMODEL + (size_t)h * DK;
    const float scale = 0.125f;       // 1/sqrt(64)
    const int qrow = warp * 16 + g;   // row pair: qrow, qrow+8

    // ---- stage Q tile into Ps, pull fragments into registers ----
    for (int e = tid; e < 64 * 16; e += 128) {   // 4-half chunks
        int r = e >> 4, d4 = (e & 15) * 4;
        *(uint2*)&Ps[r * ALD + d4] =
            *(const uint2*)(q + base + (size_t)(qt * 64 + r) * DMODEL + d4);
    }
    __syncthreads();

    uint32_t qf[4][4];
#pragma unroll
    for (int ks = 0; ks < 4; ks++) {
        const int k0 = ks * 16;
        qf[ks][0] = *(const uint32_t*)&Ps[qrow * ALD + k0 + 2 * th];
        qf[ks][1] = *(const uint32_t*)&Ps[(qrow + 8) * ALD + k0 + 2 * th];
        qf[ks][2] = *(const uint32_t*)&Ps[qrow * ALD + k0 + 2 * th + 8];
        qf[ks][3] = *(const uint32_t*)&Ps[(qrow + 8) * ALD + k0 + 2 * th + 8];
    }
    __syncthreads();

    float m0 = -1e30f, m1 = -1e30f, l0 = 0.f, l1 = 0.f;
    float o[8][4];
#pragma unroll
    for (int i = 0; i < 8; i++)
#pragma unroll
        for (int j = 0; j < 4; j++) o[i][j] = 0.f;

    for (int kt = 0; kt < SEQ / 64; kt++) {
        // load K (row-major) and V (transposed) tiles
        for (int e = tid; e < 64 * 16; e += 128) {
            int r = e >> 4, d4 = (e & 15) * 4;
            size_t go = base + (size_t)(kt * 64 + r) * DMODEL + d4;
            *(uint2*)&Ks[r * ALD + d4] = *(const uint2*)(k + go);
            uint2 vv = *(const uint2*)(v + go);
            const __half* vh = (const __half*)&vv;
            Vt[(d4 + 0) * ALD + r] = vh[0];
            Vt[(d4 + 1) * ALD + r] = vh[1];
            Vt[(d4 + 2) * ALD + r] = vh[2];
            Vt[(d4 + 3) * ALD + r] = vh[3];
        }
        __syncthreads();

        // ---- S = Q @ K^T : M=16, N=64 (kv), K=64 (d) ----
        float s[8][4];
#pragma unroll
        for (int nt = 0; nt < 8; nt++)
#pragma unroll
            for (int r = 0; r < 4; r++) s[nt][r] = 0.f;

#pragma unroll
        for (int ks = 0; ks < 4; ks++) {
            const int k0 = ks * 16;
#pragma unroll
            for (int nt = 0; nt < 8; nt++) {
                const int c0 = nt * 8 + g;
                uint32_t bf[2];
                bf[0] = *(const uint32_t*)&Ks[c0 * ALD + k0 + 2 * th];
                bf[1] = *(const uint32_t*)&Ks[c0 * ALD + k0 + 2 * th + 8];
                mma_f16(s[nt], qf[ks], bf);
            }
        }

        // ---- online softmax (rows qrow, qrow+8) ----
        float rm0 = -1e30f, rm1 = -1e30f;
#pragma unroll
        for (int nt = 0; nt < 8; nt++) {
            s[nt][0] *= scale; s[nt][1] *= scale;
            s[nt][2] *= scale; s[nt][3] *= scale;
            rm0 = fmaxf(rm0, fmaxf(s[nt][0], s[nt][1]));
            rm1 = fmaxf(rm1, fmaxf(s[nt][2], s[nt][3]));
        }
        rm0 = fmaxf(rm0, __shfl_xor_sync(0xffffffffu, rm0, 1));
        rm0 = fmaxf(rm0, __shfl_xor_sync(0xffffffffu, rm0, 2));
        rm1 = fmaxf(rm1, __shfl_xor_sync(0xffffffffu, rm1, 1));
        rm1 = fmaxf(rm1, __shfl_xor_sync(0xffffffffu, rm1, 2));

        const float mn0 = fmaxf(m0, rm0);
        const float mn1 = fmaxf(m1, rm1);
        const float corr0 = __expf(m0 - mn0);
        const float corr1 = __expf(m1 - mn1);

        float rs0 = 0.f, rs1 = 0.f;
#pragma unroll
        for (int nt = 0; nt < 8; nt++) {
            float p00 = __expf(s[nt][0] - mn0);
            float p01 = __expf(s[nt][1] - mn0);
            float p10 = __expf(s[nt][2] - mn1);
            float p11 = __expf(s[nt][3] - mn1);
            rs0 += p00 + p01;
            rs1 += p10 + p11;
            const int c0 = nt * 8 + 2 * th;
            *(__half2*)&Ps[qrow * ALD + c0]       = __floats2half2_rn(p00, p01);
            *(__half2*)&Ps[(qrow + 8) * ALD + c0] = __floats2half2_rn(p10, p11);
        }
        rs0 += __shfl_xor_sync(0xffffffffu, rs0, 1);
        rs0 += __shfl_xor_sync(0xffffffffu, rs0, 2);
        rs1 += __shfl_xor_sync(0xffffffffu, rs1, 1);
        rs1 += __shfl_xor_sync(0xffffffffu, rs1, 2);

        l0 = l0 * corr0 + rs0;
        l1 = l1 * corr1 + rs1;
        m0 = mn0;
        m1 = mn1;

#pragma unroll
        for (int dt = 0; dt < 8; dt++) {
            o[dt][0] *= corr0; o[dt][1] *= corr0;
            o[dt][2] *= corr1; o[dt][3] *= corr1;
        }
        __syncwarp();   // Ps rows are warp-private

        // ---- O += P @ V : M=16, N=64 (d), K=64 (kv) ----
#pragma unroll
        for (int ks = 0; ks < 4; ks++) {
            const int k0 = ks * 16;
            uint32_t af[4];
            af[0] = *(const uint32_t*)&Ps[qrow * ALD + k0 + 2 * th];
            af[1] = *(const uint32_t*)&Ps[(qrow + 8) * ALD + k0 + 2 * th];
            af[2] = *(const uint32_t*)&Ps[qrow * ALD + k0 + 2 * th + 8];
            af[3] = *(const uint32_t*)&Ps[(qrow + 8) * ALD + k0 + 2 * th + 8];
#pragma unroll
            for (int dt = 0; dt < 8; dt++) {
                const int c0 = dt * 8 + g;
                uint32_t bf[2];
                bf[0] = *(const uint32_t*)&Vt[c0 * ALD + k0 + 2 * th];
                bf[1] = *(const uint32_t*)&Vt[c0 * ALD + k0 + 2 * th + 8];
                mma_f16(o[dt], af, bf);
            }
        }
        __syncthreads();   // done with Ks/Vt/Ps before next tile
    }

    // epilogue -> fp16 ctx (feeds Wo GEMM)
    const float inv0 = 1.0f / l0;
    const float inv1 = 1.0f / l1;
    const size_t row0 = base + (size_t)(qt * 64 + qrow) * DMODEL;
    const size_t row1 = base + (size_t)(qt * 64 + qrow + 8) * DMODEL;
#pragma unroll
    for (int dt = 0; dt < 8; dt++) {
        const int c0 = dt * 8 + 2 * th;
        *(__half2*)(ctx + row0 + c0) = __floats2half2_rn(o[dt][0] * inv0, o[dt][1] * inv0);
        *(__half2*)(ctx + row1 + c0) = __floats2half2_rn(o[dt][2] * inv1, o[dt][3] * inv1);
    }
}

// ---------------------------------------------------------------------------
// out = LayerNorm(a + b) * gamma + beta; optional fp16 copy for next GEMM.
// ---------------------------------------------------------------------------
__global__ __launch_bounds__(256)
void add_ln_kernel(const float* __restrict__ a, const float* __restrict__ b,
                   const float* __restrict__ gamma, const float* __restrict__ beta,
                   float* __restrict__ out, __half* __restrict__ out_h) {
    const int row = blockIdx.x;
    const int tid = threadIdx.x;
    const size_t off = (size_t)row * DMODEL;

    __shared__ float r1[8], r2[8];

    float vals[4];
    float sum = 0.f, sq = 0.f;
#pragma unroll
    for (int t = 0; t < 4; t++) {
        int c = tid + t * 256;
        float vv = a[off + c] + b[off + c];
        vals[t] = vv;
        sum += vv;
        sq  += vv * vv;
    }
#pragma unroll
    for (int o = 16; o > 0; o >>= 1) {
        sum += __shfl_xor_sync(0xffffffffu, sum, o);
        sq  += __shfl_xor_sync(0xffffffffu, sq,  o);
    }
    const int wid = tid >> 5;
    if ((tid & 31) == 0) { r1[wid] = sum; r2[wid] = sq; }
    __syncthreads();
    float tot1 = 0.f, tot2 = 0.f;
#pragma unroll
    for (int w = 0; w < 8; w++) { tot1 += r1[w]; tot2 += r2[w]; }

    const float mu   = tot1 * (1.0f / DMODEL);
    const float var  = tot2 * (1.0f / DMODEL) - mu * mu;
    const float rstd = rsqrtf(var + LN_EPS);

#pragma unroll
    for (int t = 0; t < 4; t++) {
        int c = tid + t * 256;
        float y = (vals[t] - mu) * rstd * gamma[c] + beta[c];
        out[off + c] = y;
        if (out_h) out_h[off + c] = __float2half(y);
    }
}

// ---------------------------------------------------------------------------
// Launcher
// ---------------------------------------------------------------------------
extern "C" void kernel_launch(void* const* d_in, const int* in_sizes, int n_in,
                              void* d_out, int out_size) {
    (void)in_sizes; (void)n_in; (void)out_size;
    const float* x   = (const float*)d_in[0];
    const float* wq  = (const float*)d_in[1];
    const float* wk  = (const float*)d_in[2];
    const float* wv  = (const float*)d_in[3];
    const float* wo  = (const float*)d_in[4];
    const float* w1  = (const float*)d_in[5];
    const float* b1  = (const float*)d_in[6];
    const float* w2  = (const float*)d_in[7];
    const float* b2  = (const float*)d_in[8];
    const float* g1  = (const float*)d_in[9];
    const float* be1 = (const float*)d_in[10];
    const float* g2  = (const float*)d_in[11];
    const float* be2 = (const float*)d_in[12];
    float* out = (float*)d_out;

    __half *xh, *qh, *kh, *vh, *ctxh, *hrh, *ffh;
    __half *wqt, *wkt, *wvt, *wot, *w1t, *w2t;
    float *attn, *h, *f2;
    cudaGetSymbolAddress((void**)&xh,   g_xh);
    cudaGetSymbolAddress((void**)&qh,   g_qh);
    cudaGetSymbolAddress((void**)&kh,   g_kh);
    cudaGetSymbolAddress((void**)&vh,   g_vh);
    cudaGetSymbolAddress((void**)&ctxh, g_ctxh);
    cudaGetSymbolAddress((void**)&hrh,  g_hrh);
    cudaGetSymbolAddress((void**)&ffh,  g_ffh);
    cudaGetSymbolAddress((void**)&attn, g_attn);
    cudaGetSymbolAddress((void**)&h,    g_h);
    cudaGetSymbolAddress((void**)&f2,   g_f2);
    cudaGetSymbolAddress((void**)&wqt,  g_wqt);
    cudaGetSymbolAddress((void**)&wkt,  g_wkt);
    cudaGetSymbolAddress((void**)&wvt,  g_wvt);
    cudaGetSymbolAddress((void**)&wot,  g_wot);
    cudaGetSymbolAddress((void**)&w1t,  g_w1t);
    cudaGetSymbolAddress((void**)&w2t,  g_w2t);

    cudaFuncSetAttribute(hgemm<false, false, true>,
                         cudaFuncAttributeMaxDynamicSharedMemorySize, HGEMM_SMEM);
    cudaFuncSetAttribute(hgemm<false, false, false>,
                         cudaFuncAttributeMaxDynamicSharedMemorySize, HGEMM_SMEM);
    cudaFuncSetAttribute(hgemm<true, true, true>,
                         cudaFuncAttributeMaxDynamicSharedMemorySize, HGEMM_SMEM);
    cudaFuncSetAttribute(hgemm<true, false, false>,
                         cudaFuncAttributeMaxDynamicSharedMemorySize, HGEMM_SMEM);

    // ---- prep: convert x and weights to fp16 (weights transposed K-major) ----
    {
        const int n_x = NTOK * DMODEL / 4;
        f2h_kernel<<<(n_x + 255) / 256, 256>>>(x, xh, n_x);
        dim3 tb(32, 8);
        transpose_f2h_kernel<<<dim3(DMODEL / 32, DMODEL / 32), tb>>>(wq, wqt, DMODEL, DMODEL);
        transpose_f2h_kernel<<<dim3(DMODEL / 32, DMODEL / 32), tb>>>(wk, wkt, DMODEL, DMODEL);
        transpose_f2h_kernel<<<dim3(DMODEL / 32, DMODEL / 32), tb>>>(wv, wvt, DMODEL, DMODEL);
        transpose_f2h_kernel<<<dim3(DMODEL / 32, DMODEL / 32), tb>>>(wo, wot, DMODEL, DMODEL);
        transpose_f2h_kernel<<<dim3(DFF / 32,    DMODEL / 32), tb>>>(w1, w1t, DMODEL, DFF);
        transpose_f2h_kernel<<<dim3(DMODEL / 32, DFF / 32),    tb>>>(w2, w2t, DFF, DMODEL);
    }

    const dim3 g_dd(DMODEL / 128, NTOK / 128);   // (8, 64)
    const dim3 g_df(DFF / 128,    NTOK / 128);   // (32, 64)

    // Q, K, V projections -> fp16
    hgemm<false, false, true><<<g_dd, 256, HGEMM_SMEM>>>(xh, wqt, nullptr, qh, NTOK, DMODEL, DMODEL);
    hgemm<false, false, true><<<g_dd, 256, HGEMM_SMEM>>>(xh, wkt, nullptr, kh, NTOK, DMODEL, DMODEL);
    hgemm<false, false, true><<<g_dd, 256, HGEMM_SMEM>>>(xh, wvt, nullptr, vh, NTOK, DMODEL, DMODEL);

    // attention -> fp16 ctx
    flash_attn_h<<<dim3(SEQ / 64, NHEAD, BATCH), 128, AT_SMEM>>>(qh, kh, vh, ctxh);

    // output projection -> fp32
    hgemm<false, false, false><<<g_dd, 256, HGEMM_SMEM>>>(ctxh, wot, nullptr, attn, NTOK, DMODEL, DMODEL);

    // add & norm 1 (h fp32 residual, hrh fp16 for FFN1)
    add_ln_kernel<<<NTOK, 256>>>(x, attn, g1, be1, h, hrh);

    // FFN
    hgemm<true, true,  true ><<<g_df, 256, HGEMM_SMEM>>>(hrh, w1t, b1, ffh, NTOK, DFF,    DMODEL);
    hgemm<true, false, false><<<g_dd, 256, HGEMM_SMEM>>>(ffh, w2t, b2, f2,  NTOK, DMODEL, DFF);

    // add & norm 2
    add_ln_kernel<<<NTOK, 256>>>(h, f2, g2, be2, out, nullptr);
}

// round 7
// speedup vs baseline: 2.5396x; 1.3190x over previous
#include <cuda_runtime.h>
#include <cuda_fp16.h>
#include <math.h>
#include <stdint.h>

// ---------------------------------------------------------------------------
// Problem constants
// ---------------------------------------------------------------------------
#define BATCH   4
#define SEQ     2048
#define DMODEL  1024
#define NHEAD   16
#define DK      64
#define DFF     4096
#define NTOK    (BATCH * SEQ)          // 8192
#define LN_EPS  1e-5f
#define QLD     (3 * DMODEL)           // packed qkv row stride

// ---------------------------------------------------------------------------
// Scratch (device globals — allocation-free rule)
// ---------------------------------------------------------------------------
__device__ __half g_xh   [NTOK * DMODEL];
__device__ __half g_qkvh [NTOK * QLD];
__device__ __half g_ctxh [NTOK * DMODEL];
__device__ __half g_hrh  [NTOK * DMODEL];
__device__ __half g_ffh  [NTOK * DFF];
__device__ float  g_attn [NTOK * DMODEL];
__device__ float  g_h    [NTOK * DMODEL];
__device__ float  g_f2   [NTOK * DMODEL];
// fp16 K-major weights: wt[n][k] = (half)w[k][n]
__device__ __half g_wqkvt[QLD * DMODEL];       // [3072][1024] = wq^T | wk^T | wv^T
__device__ __half g_wot  [DMODEL * DMODEL];
__device__ __half g_w1t  [DFF * DMODEL];
__device__ __half g_w2t  [DMODEL * DFF];

// ---------------------------------------------------------------------------
// Helpers
// ---------------------------------------------------------------------------
__device__ __forceinline__ uint32_t smem_u32(const void* p) {
    return (uint32_t)__cvta_generic_to_shared(p);
}
__device__ __forceinline__ void cp_async16(uint32_t dst, const void* src) {
    asm volatile("cp.async.cg.shared.global [%0], [%1], 16;\n" :: "r"(dst), "l"(src));
}
__device__ __forceinline__ void cp_commit() { asm volatile("cp.async.commit_group;\n"); }
__device__ __forceinline__ void cp_wait2()  { asm volatile("cp.async.wait_group 2;\n"); }
__device__ __forceinline__ void cp_wait1()  { asm volatile("cp.async.wait_group 1;\n"); }
__device__ __forceinline__ void cp_wait0()  { asm volatile("cp.async.wait_group 0;\n"); }

// mma.m16n8k16 row.col f32 += f16 * f16
__device__ __forceinline__ void mma_f16(float* c, const uint32_t* a,
                                        uint32_t b0, uint32_t b1) {
    asm volatile(
        "mma.sync.aligned.m16n8k16.row.col.f32.f16.f16.f32 "
        "{%0,%1,%2,%3}, {%4,%5,%6,%7}, {%8,%9}, {%0,%1,%2,%3};"
        : "+f"(c[0]), "+f"(c[1]), "+f"(c[2]), "+f"(c[3])
        : "r"(a[0]), "r"(a[1]), "r"(a[2]), "r"(a[3]), "r"(b0), "r"(b1));
}

__device__ __forceinline__ void ldsm_x4(uint32_t* r, uint32_t addr) {
    asm volatile("ldmatrix.sync.aligned.m8n8.x4.shared.b16 {%0,%1,%2,%3}, [%4];"
                 : "=r"(r[0]), "=r"(r[1]), "=r"(r[2]), "=r"(r[3]) : "r"(addr));
}
__device__ __forceinline__ void ldsm_x4_trans(uint32_t* r, uint32_t addr) {
    asm volatile("ldmatrix.sync.aligned.m8n8.x4.trans.shared.b16 {%0,%1,%2,%3}, [%4];"
                 : "=r"(r[0]), "=r"(r[1]), "=r"(r[2]), "=r"(r[3]) : "r"(addr));
}

// ---------------------------------------------------------------------------
// Prep kernels: fp32 -> fp16 (optionally transposed)
// ---------------------------------------------------------------------------
__global__ __launch_bounds__(256)
void f2h_kernel(const float* __restrict__ in, __half* __restrict__ out, int n4) {
    int i = blockIdx.x * blockDim.x + threadIdx.x;
    if (i < n4) {
        float4 v = *(const float4*)(in + 4 * i);
        *(__half2*)(out + 4 * i)     = __floats2half2_rn(v.x, v.y);
        *(__half2*)(out + 4 * i + 2) = __floats2half2_rn(v.z, v.w);
    }
}

// wt[n][k] = half(w[k][n]); w is [K][N] row-major.
__global__ __launch_bounds__(256)
void transpose_f2h_kernel(const float* __restrict__ w, __half* __restrict__ wt,
                          int K, int N) {
    __shared__ float t[32][33];
    const int n0 = blockIdx.x * 32;
    const int k0 = blockIdx.y * 32;
#pragma unroll
    for (int i = threadIdx.y; i < 32; i += 8)
        t[i][threadIdx.x] = w[(size_t)(k0 + i) * N + n0 + threadIdx.x];
    __syncthreads();
#pragma unroll
    for (int i = threadIdx.y; i < 32; i += 8)
        wt[(size_t)(n0 + i) * K + k0 + threadIdx.x] = __float2half(t[threadIdx.x][i]);
}

// ---------------------------------------------------------------------------
// FP16 GEMM, ldmatrix fragments, 3-stage cp.async pipeline.
// C[M,N] = A[M,K] @ BT[N,K]^T (+bias)(+relu). 128x128 tile, BK=64, 8 warps.
// ---------------------------------------------------------------------------
#define HLD 72
#define HSTAGE_H (128 * HLD)
#define HSTAGE_ALL (2 * HSTAGE_H)
#define HGEMM_SMEM (3 * HSTAGE_ALL * (int)sizeof(__half))

template<bool BIAS, bool RELU, bool HOUT>
__global__ __launch_bounds__(256, 2)
void hgemm(const __half* __restrict__ A, const __half* __restrict__ BT,
           const float* __restrict__ bias, void* __restrict__ Cv,
           int M, int N, int K) {
    extern __shared__ __half hsm[];

    const int tid  = threadIdx.x;
    const int lane = tid & 31;
    const int warp = tid >> 5;
    const int wm   = warp & 1;
    const int wn   = warp >> 1;
    const int g    = lane >> 2;
    const int th   = lane & 3;
    const int lrow = lane & 7;
    const int lgrp = lane >> 3;

    const int rowBase = blockIdx.y * 128;
    const int colBase = blockIdx.x * 128;

    float acc[4][4][4];
#pragma unroll
    for (int i = 0; i < 4; i++)
#pragma unroll
        for (int j = 0; j < 4; j++)
#pragma unroll
            for (int r = 0; r < 4; r++) acc[i][j][r] = 0.f;

    // ldmatrix lane byte-offsets within a stage
    uint32_t aoff[4], boff[2];
#pragma unroll
    for (int mt = 0; mt < 4; mt++)
        aoff[mt] = (uint32_t)(((wm * 64 + mt * 16 + (lgrp & 1) * 8 + lrow) * HLD
                               + (lgrp >> 1) * 8) * 2);
#pragma unroll
    for (int p = 0; p < 2; p++)
        boff[p] = (uint32_t)(((wn * 32 + p * 16 + (lgrp >> 1) * 8 + lrow) * HLD
                              + (lgrp & 1) * 8) * 2 + HSTAGE_H * 2);

    auto load_chunk = [&](int c) {
        const int s = c % 3;
        __half* as = hsm + s * HSTAGE_ALL;
        __half* bs = as + HSTAGE_H;
        const size_t koff = (size_t)c * 64;
#pragma unroll
        for (int p = 0; p < 4; p++) {
            int idx = tid + p * 256;
            int r = idx >> 3, j = (idx & 7) * 8;
            cp_async16(smem_u32(as + r * HLD + j),
                       A  + (size_t)(rowBase + r) * K + koff + j);
            cp_async16(smem_u32(bs + r * HLD + j),
                       BT + (size_t)(colBase + r) * K + koff + j);
        }
        cp_commit();
    };

    const int nk = K / 64;
    load_chunk(0);
    load_chunk(1);

    for (int it = 0; it < nk; it++) {
        const int s = it % 3;
        if (it + 2 < nk) {
            load_chunk(it + 2);
            cp_wait2();
        } else if (it + 1 < nk) {
            cp_wait1();
        } else {
            cp_wait0();
        }
        __syncthreads();

        const uint32_t sbase = smem_u32(hsm + s * HSTAGE_ALL);
#pragma unroll
        for (int ks = 0; ks < 4; ks++) {
            const uint32_t k0b = (uint32_t)(ks * 32);
            uint32_t af[4][4], bf[2][4];
#pragma unroll
            for (int mt = 0; mt < 4; mt++) ldsm_x4(af[mt], sbase + aoff[mt] + k0b);
#pragma unroll
            for (int p = 0; p < 2; p++) ldsm_x4(bf[p], sbase + boff[p] + k0b);
#pragma unroll
            for (int mt = 0; mt < 4; mt++) {
                mma_f16(acc[mt][0], af[mt], bf[0][0], bf[0][1]);
                mma_f16(acc[mt][1], af[mt], bf[0][2], bf[0][3]);
                mma_f16(acc[mt][2], af[mt], bf[1][0], bf[1][1]);
                mma_f16(acc[mt][3], af[mt], bf[1][2], bf[1][3]);
            }
        }
        __syncthreads();
    }

    float* Cf = (float*)Cv;
    __half* Ch = (__half*)Cv;
#pragma unroll
    for (int mt = 0; mt < 4; mt++) {
        const int r0 = rowBase + wm * 64 + mt * 16 + g;
#pragma unroll
        for (int nt = 0; nt < 4; nt++) {
            const int c0 = colBase + wn * 32 + nt * 8 + 2 * th;
            float2 v0 = make_float2(acc[mt][nt][0], acc[mt][nt][1]);
            float2 v1 = make_float2(acc[mt][nt][2], acc[mt][nt][3]);
            if (BIAS) {
                float2 bb = *(const float2*)(bias + c0);
                v0.x += bb.x; v0.y += bb.y;
                v1.x += bb.x; v1.y += bb.y;
            }
            if (RELU) {
                v0.x = fmaxf(v0.x, 0.f); v0.y = fmaxf(v0.y, 0.f);
                v1.x = fmaxf(v1.x, 0.f); v1.y = fmaxf(v1.y, 0.f);
            }
            if (HOUT) {
                *(__half2*)(Ch + (size_t)r0 * N + c0)       = __floats2half2_rn(v0.x, v0.y);
                *(__half2*)(Ch + (size_t)(r0 + 8) * N + c0) = __floats2half2_rn(v1.x, v1.y);
            } else {
                *(float2*)(Cf + (size_t)r0 * N + c0)       = v0;
                *(float2*)(Cf + (size_t)(r0 + 8) * N + c0) = v1;
            }
        }
    }
}

// ---------------------------------------------------------------------------
// Flash attention, FP16 mma + ldmatrix, double-buffered cp.async K/V.
// Reads packed qkv [tok][3072]: q at +0, k at +1024, v at +2048.
// grid = (SEQ/64, NHEAD, BATCH), 128 threads (4 warps), 16 q-rows per warp.
// smem (halves, LD=72): K0,V0,K1,V1,Ps = 5 * 64*72*2 = 46,080 B.
// ---------------------------------------------------------------------------
#define ALD   72
#define ATILE (64 * ALD)
#define AT_SMEM (5 * ATILE * (int)sizeof(__half))

__global__ __launch_bounds__(128, 4)
void flash_attn_h(const __half* __restrict__ qkv, __half* __restrict__ ctx) {
    extern __shared__ __half asm_[];
    __half* Ps = asm_ + 4 * ATILE;

    const int tid  = threadIdx.x;
    const int lane = tid & 31;
    const int warp = tid >> 5;
    const int g    = lane >> 2;
    const int th   = lane & 3;
    const int lrow = lane & 7;
    const int lgrp = lane >> 3;
    const int qt   = blockIdx.x;
    const int h    = blockIdx.y;
    const int b    = blockIdx.z;

    const size_t base = (size_t)b * SEQ * QLD + (size_t)h * DK;
    const __half* qp = qkv + base;
    const __half* kp = qkv + base + DMODEL;
    const __half* vp = qkv + base + 2 * DMODEL;

    const float scale = 0.125f;       // 1/sqrt(64)
    const int qrow = warp * 16 + g;   // row pair: qrow, qrow+8

    // ldmatrix lane byte-offsets
    const uint32_t psbase = smem_u32(Ps);
    const uint32_t qoff = (uint32_t)(((warp * 16 + (lgrp & 1) * 8 + lrow) * ALD
                                      + (lgrp >> 1) * 8) * 2);
    uint32_t koff[4], voff[4];
#pragma unroll
    for (int p = 0; p < 4; p++) {
        koff[p] = (uint32_t)(((p * 16 + (lgrp >> 1) * 8 + lrow) * ALD
                              + (lgrp & 1) * 8) * 2);
        voff[p] = (uint32_t)((((lgrp & 1) * 8 + lrow) * ALD
                              + p * 16 + (lgrp >> 1) * 8) * 2);
    }

    // prefetch kv tile 0
    auto load_kv = [&](int kt) {
        __half* kd = asm_ + (kt & 1) * 2 * ATILE;
        __half* vd = kd + ATILE;
#pragma unroll
        for (int i = 0; i < 4; i++) {
            int c = tid + i * 128;             // 0..511
            int r = c >> 3, off = (c & 7) * 8;
            size_t go = (size_t)(kt * 64 + r) * QLD + off;
            cp_async16(smem_u32(kd + r * ALD + off), kp + go);
            cp_async16(smem_u32(vd + r * ALD + off), vp + go);
        }
        cp_commit();
    };
    load_kv(0);

    // stage Q into Ps, pull fragments
    for (int e = tid; e < 64 * 16; e += 128) {
        int r = e >> 4, d4 = (e & 15) * 4;
        *(uint2*)&Ps[r * ALD + d4] =
            *(const uint2*)(qp + (size_t)(qt * 64 + r) * QLD + d4);
    }
    __syncthreads();

    uint32_t qf[4][4];
#pragma unroll
    for (int ks = 0; ks < 4; ks++)
        ldsm_x4(qf[ks], psbase + qoff + ks * 32);
    __syncthreads();

    float m0 = -1e30f, m1 = -1e30f, l0 = 0.f, l1 = 0.f;
    float o[8][4];
#pragma unroll
    for (int i = 0; i < 8; i++)
#pragma unroll
        for (int j = 0; j < 4; j++) o[i][j] = 0.f;

    for (int kt = 0; kt < SEQ / 64; kt++) {
        if (kt + 1 < SEQ / 64) {
            load_kv(kt + 1);
            cp_wait1();
        } else {
            cp_wait0();
        }
        __syncthreads();

        const uint32_t kbase = smem_u32(asm_ + (kt & 1) * 2 * ATILE);
        const uint32_t vbase = kbase + ATILE * 2;   // bytes

        // ---- S = Q @ K^T ----
        float s[8][4];
#pragma unroll
        for (int nt = 0; nt < 8; nt++)
#pragma unroll
            for (int r = 0; r < 4; r++) s[nt][r] = 0.f;

#pragma unroll
        for (int ks = 0; ks < 4; ks++) {
            const uint32_t k0b = ks * 32;
#pragma unroll
            for (int p = 0; p < 4; p++) {
                uint32_t kf[4];
                ldsm_x4(kf, kbase + koff[p] + k0b);
                mma_f16(s[2 * p],     qf[ks], kf[0], kf[1]);
                mma_f16(s[2 * p + 1], qf[ks], kf[2], kf[3]);
            }
        }

        // ---- online softmax ----
        float rm0 = -1e30f, rm1 = -1e30f;
#pragma unroll
        for (int nt = 0; nt < 8; nt++) {
            s[nt][0] *= scale; s[nt][1] *= scale;
            s[nt][2] *= scale; s[nt][3] *= scale;
            rm0 = fmaxf(rm0, fmaxf(s[nt][0], s[nt][1]));
            rm1 = fmaxf(rm1, fmaxf(s[nt][2], s[nt][3]));
        }
        rm0 = fmaxf(rm0, __shfl_xor_sync(0xffffffffu, rm0, 1));
        rm0 = fmaxf(rm0, __shfl_xor_sync(0xffffffffu, rm0, 2));
        rm1 = fmaxf(rm1, __shfl_xor_sync(0xffffffffu, rm1, 1));
        rm1 = fmaxf(rm1, __shfl_xor_sync(0xffffffffu, rm1, 2));

        const float mn0 = fmaxf(m0, rm0);
        const float mn1 = fmaxf(m1, rm1);
        const float corr0 = __expf(m0 - mn0);
        const float corr1 = __expf(m1 - mn1);

        float rs0 = 0.f, rs1 = 0.f;
#pragma unroll
        for (int nt = 0; nt < 8; nt++) {
            float p00 = __expf(s[nt][0] - mn0);
            float p01 = __expf(s[nt][1] - mn0);
            float p10 = __expf(s[nt][2] - mn1);
            float p11 = __expf(s[nt][3] - mn1);
            rs0 += p00 + p01;
            rs1 += p10 + p11;
            const int c0 = nt * 8 + 2 * th;
            *(__half2*)&Ps[qrow * ALD + c0]       = __floats2half2_rn(p00, p01);
            *(__half2*)&Ps[(qrow + 8) * ALD + c0] = __floats2half2_rn(p10, p11);
        }
        rs0 += __shfl_xor_sync(0xffffffffu, rs0, 1);
        rs0 += __shfl_xor_sync(0xffffffffu, rs0, 2);
        rs1 += __shfl_xor_sync(0xffffffffu, rs1, 1);
        rs1 += __shfl_xor_sync(0xffffffffu, rs1, 2);

        l0 = l0 * corr0 + rs0;
        l1 = l1 * corr1 + rs1;
        m0 = mn0;
        m1 = mn1;

#pragma unroll
        for (int dt = 0; dt < 8; dt++) {
            o[dt][0] *= corr0; o[dt][1] *= corr0;
            o[dt][2] *= corr1; o[dt][3] *= corr1;
        }
        __syncwarp();   // Ps rows are warp-private

        // ---- O += P @ V (V row-major, ldmatrix.trans) ----
#pragma unroll
        for (int ks = 0; ks < 4; ks++) {
            uint32_t af[4];
            ldsm_x4(af, psbase + qoff + ks * 32);
            const uint32_t kvb = (uint32_t)(ks * 16 * ALD * 2);
#pragma unroll
            for (int p = 0; p < 4; p++) {
                uint32_t vf[4];
                ldsm_x4_trans(vf, vbase + voff[p] + kvb);
                mma_f16(o[2 * p],     af, vf[0], vf[1]);
                mma_f16(o[2 * p + 1], af, vf[2], vf[3]);
            }
        }
        __syncthreads();   // protect K/V buffer before next prefetch overwrite
    }

    // epilogue -> fp16 ctx (stride DMODEL)
    const float inv0 = 1.0f / l0;
    const float inv1 = 1.0f / l1;
    const size_t cbase = (size_t)b * SEQ * DMODEL + (size_t)h * DK;
    const size_t row0 = cbase + (size_t)(qt * 64 + qrow) * DMODEL;
    const size_t row1 = cbase + (size_t)(qt * 64 + qrow + 8) * DMODEL;
#pragma unroll
    for (int dt = 0; dt < 8; dt++) {
        const int c0 = dt * 8 + 2 * th;
        *(__half2*)(ctx + row0 + c0) = __floats2half2_rn(o[dt][0] * inv0, o[dt][1] * inv0);
        *(__half2*)(ctx + row1 + c0) = __floats2half2_rn(o[dt][2] * inv1, o[dt][3] * inv1);
    }
}

// ---------------------------------------------------------------------------
// out = LayerNorm(a + b) * gamma + beta; optional fp16 copy for next GEMM.
// ---------------------------------------------------------------------------
__global__ __launch_bounds__(256)
void add_ln_kernel(const float* __restrict__ a, const float* __restrict__ b,
                   const float* __restrict__ gamma, const float* __restrict__ beta,
                   float* __restrict__ out, __half* __restrict__ out_h) {
    const int row = blockIdx.x;
    const int tid = threadIdx.x;
    const size_t off = (size_t)row * DMODEL;

    __shared__ float r1[8], r2[8];

    float vals[4];
    float sum = 0.f, sq = 0.f;
#pragma unroll
    for (int t = 0; t < 4; t++) {
        int c = tid + t * 256;
        float vv = a[off + c] + b[off + c];
        vals[t] = vv;
        sum += vv;
        sq  += vv * vv;
    }
#pragma unroll
    for (int o = 16; o > 0; o >>= 1) {
        sum += __shfl_xor_sync(0xffffffffu, sum, o);
        sq  += __shfl_xor_sync(0xffffffffu, sq,  o);
    }
    const int wid = tid >> 5;
    if ((tid & 31) == 0) { r1[wid] = sum; r2[wid] = sq; }
    __syncthreads();
    float tot1 = 0.f, tot2 = 0.f;
#pragma unroll
    for (int w = 0; w < 8; w++) { tot1 += r1[w]; tot2 += r2[w]; }

    const float mu   = tot1 * (1.0f / DMODEL);
    const float var  = tot2 * (1.0f / DMODEL) - mu * mu;
    const float rstd = rsqrtf(var + LN_EPS);

#pragma unroll
    for (int t = 0; t < 4; t++) {
        int c = tid + t * 256;
        float y = (vals[t] - mu) * rstd * gamma[c] + beta[c];
        out[off + c] = y;
        if (out_h) out_h[off + c] = __float2half(y);
    }
}

// ---------------------------------------------------------------------------
// Launcher
// ---------------------------------------------------------------------------
extern "C" void kernel_launch(void* const* d_in, const int* in_sizes, int n_in,
                              void* d_out, int out_size) {
    (void)in_sizes; (void)n_in; (void)out_size;
    const float* x   = (const float*)d_in[0];
    const float* wq  = (const float*)d_in[1];
    const float* wk  = (const float*)d_in[2];
    const float* wv  = (const float*)d_in[3];
    const float* wo  = (const float*)d_in[4];
    const float* w1  = (const float*)d_in[5];
    const float* b1  = (const float*)d_in[6];
    const float* w2  = (const float*)d_in[7];
    const float* b2  = (const float*)d_in[8];
    const float* g1  = (const float*)d_in[9];
    const float* be1 = (const float*)d_in[10];
    const float* g2  = (const float*)d_in[11];
    const float* be2 = (const float*)d_in[12];
    float* out = (float*)d_out;

    __half *xh, *qkvh, *ctxh, *hrh, *ffh, *wqkvt, *wot, *w1t, *w2t;
    float *attn, *h, *f2;
    cudaGetSymbolAddress((void**)&xh,    g_xh);
    cudaGetSymbolAddress((void**)&qkvh,  g_qkvh);
    cudaGetSymbolAddress((void**)&ctxh,  g_ctxh);
    cudaGetSymbolAddress((void**)&hrh,   g_hrh);
    cudaGetSymbolAddress((void**)&ffh,   g_ffh);
    cudaGetSymbolAddress((void**)&attn,  g_attn);
    cudaGetSymbolAddress((void**)&h,     g_h);
    cudaGetSymbolAddress((void**)&f2,    g_f2);
    cudaGetSymbolAddress((void**)&wqkvt, g_wqkvt);
    cudaGetSymbolAddress((void**)&wot,   g_wot);
    cudaGetSymbolAddress((void**)&w1t,   g_w1t);
    cudaGetSymbolAddress((void**)&w2t,   g_w2t);

    cudaFuncSetAttribute(hgemm<false, false, true>,
                         cudaFuncAttributeMaxDynamicSharedMemorySize, HGEMM_SMEM);
    cudaFuncSetAttribute(hgemm<false, false, false>,
                         cudaFuncAttributeMaxDynamicSharedMemorySize, HGEMM_SMEM);
    cudaFuncSetAttribute(hgemm<true, true, true>,
                         cudaFuncAttributeMaxDynamicSharedMemorySize, HGEMM_SMEM);
    cudaFuncSetAttribute(hgemm<true, false, false>,
                         cudaFuncAttributeMaxDynamicSharedMemorySize, HGEMM_SMEM);
    cudaFuncSetAttribute(flash_attn_h,
                         cudaFuncAttributeMaxDynamicSharedMemorySize, AT_SMEM);

    // ---- prep: x -> fp16; weights -> fp16 K-major (qkv concatenated) ----
    {
        const int n_x = NTOK * DMODEL / 4;
        f2h_kernel<<<(n_x + 255) / 256, 256>>>(x, xh, n_x);
        dim3 tb(32, 8);
        dim3 gd(DMODEL / 32, DMODEL / 32);
        transpose_f2h_kernel<<<gd, tb>>>(wq, wqkvt,                          DMODEL, DMODEL);
        transpose_f2h_kernel<<<gd, tb>>>(wk, wqkvt + DMODEL * DMODEL,        DMODEL, DMODEL);
        transpose_f2h_kernel<<<gd, tb>>>(wv, wqkvt + 2 * DMODEL * DMODEL,    DMODEL, DMODEL);
        transpose_f2h_kernel<<<gd, tb>>>(wo, wot, DMODEL, DMODEL);
        transpose_f2h_kernel<<<dim3(DFF / 32,    DMODEL / 32), tb>>>(w1, w1t, DMODEL, DFF);
        transpose_f2h_kernel<<<dim3(DMODEL / 32, DFF / 32),    tb>>>(w2, w2t, DFF, DMODEL);
    }

    const dim3 g_qkv(QLD / 128,    NTOK / 128);   // (24, 64)
    const dim3 g_dd (DMODEL / 128, NTOK / 128);   // (8, 64)
    const dim3 g_df (DFF / 128,    NTOK / 128);   // (32, 64)

    // fused QKV projection -> packed fp16 [tok][3072]
    hgemm<false, false, true><<<g_qkv, 256, HGEMM_SMEM>>>(xh, wqkvt, nullptr, qkvh,
                                                          NTOK, QLD, DMODEL);

    // attention -> fp16 ctx
    flash_attn_h<<<dim3(SEQ / 64, NHEAD, BATCH), 128, AT_SMEM>>>(qkvh, ctxh);

    // output projection -> fp32
    hgemm<false, false, false><<<g_dd, 256, HGEMM_SMEM>>>(ctxh, wot, nullptr, attn,
                                                          NTOK, DMODEL, DMODEL);

    // add & norm 1 (h fp32 residual, hrh fp16 for FFN1)
    add_ln_kernel<<<NTOK, 256>>>(x, attn, g1, be1, h, hrh);

    // FFN
    hgemm<true, true,  true ><<<g_df, 256, HGEMM_SMEM>>>(hrh, w1t, b1, ffh, NTOK, DFF,    DMODEL);
    hgemm<true, false, false><<<g_dd, 256, HGEMM_SMEM>>>(ffh, w2t, b2, f2,  NTOK, DMODEL, DFF);

    // add & norm 2
    add_ln_kernel<<<NTOK, 256>>>(h, f2, g2, be2, out, nullptr);
}

// round 8
// speedup vs baseline: 2.5529x; 1.0052x over previous
#include <cuda_runtime.h>
#include <cuda_fp16.h>
#include <math.h>
#include <stdint.h>

// ---------------------------------------------------------------------------
// Problem constants
// ---------------------------------------------------------------------------
#define BATCH   4
#define SEQ     2048
#define DMODEL  1024
#define NHEAD   16
#define DK      64
#define DFF     4096
#define NTOK    (BATCH * SEQ)          // 8192
#define LN_EPS  1e-5f
#define QLD     (3 * DMODEL)           // packed qkv row stride

// ---------------------------------------------------------------------------
// Scratch (device globals — allocation-free rule)
// ---------------------------------------------------------------------------
__device__ __half g_xh   [NTOK * DMODEL];
__device__ __half g_qkvh [NTOK * QLD];
__device__ __half g_ctxh [NTOK * DMODEL];
__device__ __half g_hrh  [NTOK * DMODEL];
__device__ __half g_ffh  [NTOK * DFF];
__device__ float  g_attn [NTOK * DMODEL];
__device__ float  g_h    [NTOK * DMODEL];
__device__ float  g_f2   [NTOK * DMODEL];
// fp16 ROW-MAJOR weights (no transpose): wh[k][n] = (half)w[k][n]
__device__ __half g_wqkvh[DMODEL * QLD];       // [1024][3072] = wq | wk | wv
__device__ __half g_woh  [DMODEL * DMODEL];
__device__ __half g_w1h  [DMODEL * DFF];
__device__ __half g_w2h  [DFF * DMODEL];

// ---------------------------------------------------------------------------
// Helpers
// ---------------------------------------------------------------------------
__device__ __forceinline__ uint32_t smem_u32(const void* p) {
    return (uint32_t)__cvta_generic_to_shared(p);
}
__device__ __forceinline__ void cp_async16(uint32_t dst, const void* src) {
    asm volatile("cp.async.cg.shared.global [%0], [%1], 16;\n" :: "r"(dst), "l"(src));
}
__device__ __forceinline__ void cp_commit() { asm volatile("cp.async.commit_group;\n"); }
__device__ __forceinline__ void cp_wait2()  { asm volatile("cp.async.wait_group 2;\n"); }
__device__ __forceinline__ void cp_wait1()  { asm volatile("cp.async.wait_group 1;\n"); }
__device__ __forceinline__ void cp_wait0()  { asm volatile("cp.async.wait_group 0;\n"); }

// mma.m16n8k16 row.col f32 += f16 * f16
__device__ __forceinline__ void mma_f16(float* c, const uint32_t* a,
                                        uint32_t b0, uint32_t b1) {
    asm volatile(
        "mma.sync.aligned.m16n8k16.row.col.f32.f16.f16.f32 "
        "{%0,%1,%2,%3}, {%4,%5,%6,%7}, {%8,%9}, {%0,%1,%2,%3};"
        : "+f"(c[0]), "+f"(c[1]), "+f"(c[2]), "+f"(c[3])
        : "r"(a[0]), "r"(a[1]), "r"(a[2]), "r"(a[3]), "r"(b0), "r"(b1));
}

__device__ __forceinline__ void ldsm_x4(uint32_t* r, uint32_t addr) {
    asm volatile("ldmatrix.sync.aligned.m8n8.x4.shared.b16 {%0,%1,%2,%3}, [%4];"
                 : "=r"(r[0]), "=r"(r[1]), "=r"(r[2]), "=r"(r[3]) : "r"(addr));
}
__device__ __forceinline__ void ldsm_x4_trans(uint32_t* r, uint32_t addr) {
    asm volatile("ldmatrix.sync.aligned.m8n8.x4.trans.shared.b16 {%0,%1,%2,%3}, [%4];"
                 : "=r"(r[0]), "=r"(r[1]), "=r"(r[2]), "=r"(r[3]) : "r"(addr));
}

// ---------------------------------------------------------------------------
// Prep kernels: fp32 -> fp16, streaming (no transpose)
// ---------------------------------------------------------------------------
__global__ __launch_bounds__(256)
void f2h_kernel(const float* __restrict__ in, __half* __restrict__ out, int n4) {
    int i = blockIdx.x * blockDim.x + threadIdx.x;
    if (i < n4) {
        float4 v = *(const float4*)(in + 4 * i);
        *(__half2*)(out + 4 * i)     = __floats2half2_rn(v.x, v.y);
        *(__half2*)(out + 4 * i + 2) = __floats2half2_rn(v.z, v.w);
    }
}

// out[k][off + n] = half(in[k][n]); in [K][N] row-major, out row stride outLD.
__global__ __launch_bounds__(256)
void f2h_pack_kernel(const float* __restrict__ in, __half* __restrict__ out,
                     int N, int outLD, int off, int n4) {
    int i = blockIdx.x * blockDim.x + threadIdx.x;
    if (i < n4) {
        int nq  = N >> 2;
        int row = i / nq, c4 = (i - row * nq) * 4;
        float4 v = *(const float4*)(in + (size_t)row * N + c4);
        __half* o = out + (size_t)row * outLD + off + c4;
        *(__half2*)o       = __floats2half2_rn(v.x, v.y);
        *(__half2*)(o + 2) = __floats2half2_rn(v.z, v.w);
    }
}

// ---------------------------------------------------------------------------
// FP16 GEMM, ldmatrix fragments, 3-stage cp.async pipeline.
// C[M,N] = A[M,K] @ B[K,N] (+bias)(+relu). A row-major (K-major), B row-major
// (N-major, fragments via ldmatrix.trans). 128x128 tile, BK=64, 8 warps.
// smem/stage: A 128x72 + B 64x136 halves = 35,840 B; 3 stages = 107,520 B.
// ---------------------------------------------------------------------------
#define HLD  72
#define BLD  136
#define HA_H (128 * HLD)               // A halves per stage
#define HB_H (64 * BLD)                // B halves per stage
#define HSTAGE_ALL (HA_H + HB_H)
#define HGEMM_SMEM (3 * HSTAGE_ALL * (int)sizeof(__half))

template<bool BIAS, bool RELU, bool HOUT>
__global__ __launch_bounds__(256, 2)
void hgemm(const __half* __restrict__ A, const __half* __restrict__ B,
           const float* __restrict__ bias, void* __restrict__ Cv,
           int M, int N, int K) {
    extern __shared__ __half hsm[];

    const int tid  = threadIdx.x;
    const int lane = tid & 31;
    const int warp = tid >> 5;
    const int wm   = warp & 1;
    const int wn   = warp >> 1;
    const int g    = lane >> 2;
    const int th   = lane & 3;
    const int lrow = lane & 7;
    const int lgrp = lane >> 3;

    const int rowBase = blockIdx.y * 128;
    const int colBase = blockIdx.x * 128;

    float acc[4][4][4];
#pragma unroll
    for (int i = 0; i < 4; i++)
#pragma unroll
        for (int j = 0; j < 4; j++)
#pragma unroll
            for (int r = 0; r < 4; r++) acc[i][j][r] = 0.f;

    // ldmatrix lane byte-offsets within a stage
    uint32_t aoff[4], boff[2];
#pragma unroll
    for (int mt = 0; mt < 4; mt++)
        aoff[mt] = (uint32_t)(((wm * 64 + mt * 16 + (lgrp & 1) * 8 + lrow) * HLD
                               + (lgrp >> 1) * 8) * 2);
    // B [k][n] row-major, trans-ldmatrix (same pattern as attention V)
#pragma unroll
    for (int p = 0; p < 2; p++)
        boff[p] = (uint32_t)((((lgrp & 1) * 8 + lrow) * BLD
                              + wn * 32 + p * 16 + (lgrp >> 1) * 8) * 2
                             + HA_H * 2);

    auto load_chunk = [&](int c) {
        const int s = c % 3;
        __half* as = hsm + s * HSTAGE_ALL;
        __half* bs = as + HA_H;
        const size_t koff = (size_t)c * 64;
#pragma unroll
        for (int p = 0; p < 4; p++) {
            int idx = tid + p * 256;            // 0..1023
            // A: 128 rows x 64 halves
            int ra = idx >> 3, ja = (idx & 7) * 8;
            cp_async16(smem_u32(as + ra * HLD + ja),
                       A + (size_t)(rowBase + ra) * K + koff + ja);
            // B: 64 rows x 128 halves
            int rb = idx >> 4, jb = (idx & 15) * 8;
            cp_async16(smem_u32(bs + rb * BLD + jb),
                       B + (koff + rb) * N + colBase + jb);
        }
        cp_commit();
    };

    const int nk = K / 64;
    load_chunk(0);
    load_chunk(1);

    for (int it = 0; it < nk; it++) {
        const int s = it % 3;
        if (it + 2 < nk) {
            load_chunk(it + 2);
            cp_wait2();
        } else if (it + 1 < nk) {
            cp_wait1();
        } else {
            cp_wait0();
        }
        __syncthreads();

        const uint32_t sbase = smem_u32(hsm + s * HSTAGE_ALL);
#pragma unroll
        for (int ks = 0; ks < 4; ks++) {
            uint32_t af[4][4], bf[2][4];
#pragma unroll
            for (int mt = 0; mt < 4; mt++)
                ldsm_x4(af[mt], sbase + aoff[mt] + ks * 32);
#pragma unroll
            for (int p = 0; p < 2; p++)
                ldsm_x4_trans(bf[p], sbase + boff[p] + (uint32_t)(ks * 16 * BLD * 2));
#pragma unroll
            for (int mt = 0; mt < 4; mt++) {
                mma_f16(acc[mt][0], af[mt], bf[0][0], bf[0][1]);
                mma_f16(acc[mt][1], af[mt], bf[0][2], bf[0][3]);
                mma_f16(acc[mt][2], af[mt], bf[1][0], bf[1][1]);
                mma_f16(acc[mt][3], af[mt], bf[1][2], bf[1][3]);
            }
        }
        __syncthreads();
    }

    float* Cf = (float*)Cv;
    __half* Ch = (__half*)Cv;
#pragma unroll
    for (int mt = 0; mt < 4; mt++) {
        const int r0 = rowBase + wm * 64 + mt * 16 + g;
#pragma unroll
        for (int nt = 0; nt < 4; nt++) {
            const int c0 = colBase + wn * 32 + nt * 8 + 2 * th;
            float2 v0 = make_float2(acc[mt][nt][0], acc[mt][nt][1]);
            float2 v1 = make_float2(acc[mt][nt][2], acc[mt][nt][3]);
            if (BIAS) {
                float2 bb = *(const float2*)(bias + c0);
                v0.x += bb.x; v0.y += bb.y;
                v1.x += bb.x; v1.y += bb.y;
            }
            if (RELU) {
                v0.x = fmaxf(v0.x, 0.f); v0.y = fmaxf(v0.y, 0.f);
                v1.x = fmaxf(v1.x, 0.f); v1.y = fmaxf(v1.y, 0.f);
            }
            if (HOUT) {
                *(__half2*)(Ch + (size_t)r0 * N + c0)       = __floats2half2_rn(v0.x, v0.y);
                *(__half2*)(Ch + (size_t)(r0 + 8) * N + c0) = __floats2half2_rn(v1.x, v1.y);
            } else {
                *(float2*)(Cf + (size_t)r0 * N + c0)       = v0;
                *(float2*)(Cf + (size_t)(r0 + 8) * N + c0) = v1;
            }
        }
    }
}

// ---------------------------------------------------------------------------
// Flash attention, FP16 mma + ldmatrix, BQ=128, double-buffered cp.async K/V.
// Reads packed qkv [tok][3072]: q at +0, k at +1024, v at +2048.
// grid = (SEQ/128, NHEAD, BATCH), 256 threads (8 warps), 16 q-rows per warp.
// smem (halves, LD=72): K0,V0,K1,V1 (64 rows) + Ps (128 rows) = 55,296 B.
// ---------------------------------------------------------------------------
#define ALD   72
#define ATILE (64 * ALD)
#define AT_SMEM ((4 * ATILE + 128 * ALD) * (int)sizeof(__half))

__global__ __launch_bounds__(256, 2)
void flash_attn_h(const __half* __restrict__ qkv, __half* __restrict__ ctx) {
    extern __shared__ __half asm_[];
    __half* Ps = asm_ + 4 * ATILE;     // [128][72]

    const int tid  = threadIdx.x;
    const int lane = tid & 31;
    const int warp = tid >> 5;         // 0..7 -> 16 q rows each
    const int g    = lane >> 2;
    const int th   = lane & 3;
    const int lrow = lane & 7;
    const int lgrp = lane >> 3;
    const int qt   = blockIdx.x;
    const int h    = blockIdx.y;
    const int b    = blockIdx.z;

    const size_t base = (size_t)b * SEQ * QLD + (size_t)h * DK;
    const __half* qp = qkv + base;
    const __half* kp = qkv + base + DMODEL;
    const __half* vp = qkv + base + 2 * DMODEL;

    const float scale = 0.125f;        // 1/sqrt(64)
    const int qrow = warp * 16 + g;    // row pair: qrow, qrow+8

    const uint32_t psbase = smem_u32(Ps);
    const uint32_t qoff = (uint32_t)(((warp * 16 + (lgrp & 1) * 8 + lrow) * ALD
                                      + (lgrp >> 1) * 8) * 2);
    uint32_t koff[4], voff[4];
#pragma unroll
    for (int p = 0; p < 4; p++) {
        koff[p] = (uint32_t)(((p * 16 + (lgrp >> 1) * 8 + lrow) * ALD
                              + (lgrp & 1) * 8) * 2);
        voff[p] = (uint32_t)((((lgrp & 1) * 8 + lrow) * ALD
                              + p * 16 + (lgrp >> 1) * 8) * 2);
    }

    auto load_kv = [&](int kt) {
        __half* kd = asm_ + (kt & 1) * 2 * ATILE;
        __half* vd = kd + ATILE;
#pragma unroll
        for (int i = 0; i < 2; i++) {
            int c = tid + i * 256;              // 0..511
            int r = c >> 3, off = (c & 7) * 8;
            size_t go = (size_t)(kt * 64 + r) * QLD + off;
            cp_async16(smem_u32(kd + r * ALD + off), kp + go);
            cp_async16(smem_u32(vd + r * ALD + off), vp + go);
        }
        cp_commit();
    };
    load_kv(0);

    // stage Q (128 rows) into Ps, pull fragments
    for (int e = tid; e < 128 * 16; e += 256) {
        int r = e >> 4, d4 = (e & 15) * 4;
        *(uint2*)&Ps[r * ALD + d4] =
            *(const uint2*)(qp + (size_t)(qt * 128 + r) * QLD + d4);
    }
    __syncthreads();

    uint32_t qf[4][4];
#pragma unroll
    for (int ks = 0; ks < 4; ks++)
        ldsm_x4(qf[ks], psbase + qoff + ks * 32);
    __syncthreads();

    float m0 = -1e30f, m1 = -1e30f, l0 = 0.f, l1 = 0.f;
    float o[8][4];
#pragma unroll
    for (int i = 0; i < 8; i++)
#pragma unroll
        for (int j = 0; j < 4; j++) o[i][j] = 0.f;

    for (int kt = 0; kt < SEQ / 64; kt++) {
        if (kt + 1 < SEQ / 64) {
            load_kv(kt + 1);
            cp_wait1();
        } else {
            cp_wait0();
        }
        __syncthreads();

        const uint32_t kbase = smem_u32(asm_ + (kt & 1) * 2 * ATILE);
        const uint32_t vbase = kbase + ATILE * 2;   // bytes

        // ---- S = Q @ K^T ----
        float s[8][4];
#pragma unroll
        for (int nt = 0; nt < 8; nt++)
#pragma unroll
            for (int r = 0; r < 4; r++) s[nt][r] = 0.f;

#pragma unroll
        for (int ks = 0; ks < 4; ks++) {
            const uint32_t k0b = ks * 32;
#pragma unroll
            for (int p = 0; p < 4; p++) {
                uint32_t kf[4];
                ldsm_x4(kf, kbase + koff[p] + k0b);
                mma_f16(s[2 * p],     qf[ks], kf[0], kf[1]);
                mma_f16(s[2 * p + 1], qf[ks], kf[2], kf[3]);
            }
        }

        // ---- online softmax ----
        float rm0 = -1e30f, rm1 = -1e30f;
#pragma unroll
        for (int nt = 0; nt < 8; nt++) {
            s[nt][0] *= scale; s[nt][1] *= scale;
            s[nt][2] *= scale; s[nt][3] *= scale;
            rm0 = fmaxf(rm0, fmaxf(s[nt][0], s[nt][1]));
            rm1 = fmaxf(rm1, fmaxf(s[nt][2], s[nt][3]));
        }
        rm0 = fmaxf(rm0, __shfl_xor_sync(0xffffffffu, rm0, 1));
        rm0 = fmaxf(rm0, __shfl_xor_sync(0xffffffffu, rm0, 2));
        rm1 = fmaxf(rm1, __shfl_xor_sync(0xffffffffu, rm1, 1));
        rm1 = fmaxf(rm1, __shfl_xor_sync(0xffffffffu, rm1, 2));

        const float mn0 = fmaxf(m0, rm0);
        const float mn1 = fmaxf(m1, rm1);
        const float corr0 = __expf(m0 - mn0);
        const float corr1 = __expf(m1 - mn1);

        float rs0 = 0.f, rs1 = 0.f;
#pragma unroll
        for (int nt = 0; nt < 8; nt++) {
            float p00 = __expf(s[nt][0] - mn0);
            float p01 = __expf(s[nt][1] - mn0);
            float p10 = __expf(s[nt][2] - mn1);
            float p11 = __expf(s[nt][3] - mn1);
            rs0 += p00 + p01;
            rs1 += p10 + p11;
            const int c0 = nt * 8 + 2 * th;
            *(__half2*)&Ps[qrow * ALD + c0]       = __floats2half2_rn(p00, p01);
            *(__half2*)&Ps[(qrow + 8) * ALD + c0] = __floats2half2_rn(p10, p11);
        }
        rs0 += __shfl_xor_sync(0xffffffffu, rs0, 1);
        rs0 += __shfl_xor_sync(0xffffffffu, rs0, 2);
        rs1 += __shfl_xor_sync(0xffffffffu, rs1, 1);
        rs1 += __shfl_xor_sync(0xffffffffu, rs1, 2);

        l0 = l0 * corr0 + rs0;
        l1 = l1 * corr1 + rs1;
        m0 = mn0;
        m1 = mn1;

#pragma unroll
        for (int dt = 0; dt < 8; dt++) {
            o[dt][0] *= corr0; o[dt][1] *= corr0;
            o[dt][2] *= corr1; o[dt][3] *= corr1;
        }
        __syncwarp();   // Ps rows are warp-private

        // ---- O += P @ V (V row-major, ldmatrix.trans) ----
#pragma unroll
        for (int ks = 0; ks < 4; ks++) {
            uint32_t af[4];
            ldsm_x4(af, psbase + qoff + ks * 32);
            const uint32_t kvb = (uint32_t)(ks * 16 * ALD * 2);
#pragma unroll
            for (int p = 0; p < 4; p++) {
                uint32_t vf[4];
                ldsm_x4_trans(vf, vbase + voff[p] + kvb);
                mma_f16(o[2 * p],     af, vf[0], vf[1]);
                mma_f16(o[2 * p + 1], af, vf[2], vf[3]);
            }
        }
        __syncthreads();   // protect K/V buffer before next prefetch overwrite
    }

    // epilogue -> fp16 ctx (stride DMODEL)
    const float inv0 = 1.0f / l0;
    const float inv1 = 1.0f / l1;
    const size_t cbase = (size_t)b * SEQ * DMODEL + (size_t)h * DK;
    const size_t row0 = cbase + (size_t)(qt * 128 + qrow) * DMODEL;
    const size_t row1 = cbase + (size_t)(qt * 128 + qrow + 8) * DMODEL;
#pragma unroll
    for (int dt = 0; dt < 8; dt++) {
        const int c0 = dt * 8 + 2 * th;
        *(__half2*)(ctx + row0 + c0) = __floats2half2_rn(o[dt][0] * inv0, o[dt][1] * inv0);
        *(__half2*)(ctx + row1 + c0) = __floats2half2_rn(o[dt][2] * inv1, o[dt][3] * inv1);
    }
}

// ---------------------------------------------------------------------------
// out = LayerNorm(a + b) * gamma + beta; optional fp16 copy for next GEMM.
// ---------------------------------------------------------------------------
__global__ __launch_bounds__(256)
void add_ln_kernel(const float* __restrict__ a, const float* __restrict__ b,
                   const float* __restrict__ gamma, const float* __restrict__ beta,
                   float* __restrict__ out, __half* __restrict__ out_h) {
    const int row = blockIdx.x;
    const int tid = threadIdx.x;
    const size_t off = (size_t)row * DMODEL;

    __shared__ float r1[8], r2[8];

    float vals[4];
    float sum = 0.f, sq = 0.f;
#pragma unroll
    for (int t = 0; t < 4; t++) {
        int c = tid + t * 256;
        float vv = a[off + c] + b[off + c];
        vals[t] = vv;
        sum += vv;
        sq  += vv * vv;
    }
#pragma unroll
    for (int o = 16; o > 0; o >>= 1) {
        sum += __shfl_xor_sync(0xffffffffu, sum, o);
        sq  += __shfl_xor_sync(0xffffffffu, sq,  o);
    }
    const int wid = tid >> 5;
    if ((tid & 31) == 0) { r1[wid] = sum; r2[wid] = sq; }
    __syncthreads();
    float tot1 = 0.f, tot2 = 0.f;
#pragma unroll
    for (int w = 0; w < 8; w++) { tot1 += r1[w]; tot2 += r2[w]; }

    const float mu   = tot1 * (1.0f / DMODEL);
    const float var  = tot2 * (1.0f / DMODEL) - mu * mu;
    const float rstd = rsqrtf(var + LN_EPS);

#pragma unroll
    for (int t = 0; t < 4; t++) {
        int c = tid + t * 256;
        float y = (vals[t] - mu) * rstd * gamma[c] + beta[c];
        out[off + c] = y;
        if (out_h) out_h[off + c] = __float2half(y);
    }
}

// ---------------------------------------------------------------------------
// Launcher
// ---------------------------------------------------------------------------
extern "C" void kernel_launch(void* const* d_in, const int* in_sizes, int n_in,
                              void* d_out, int out_size) {
    (void)in_sizes; (void)n_in; (void)out_size;
    const float* x   = (const float*)d_in[0];
    const float* wq  = (const float*)d_in[1];
    const float* wk  = (const float*)d_in[2];
    const float* wv  = (const float*)d_in[3];
    const float* wo  = (const float*)d_in[4];
    const float* w1  = (const float*)d_in[5];
    const float* b1  = (const float*)d_in[6];
    const float* w2  = (const float*)d_in[7];
    const float* b2  = (const float*)d_in[8];
    const float* g1  = (const float*)d_in[9];
    const float* be1 = (const float*)d_in[10];
    const float* g2  = (const float*)d_in[11];
    const float* be2 = (const float*)d_in[12];
    float* out = (float*)d_out;

    __half *xh, *qkvh, *ctxh, *hrh, *ffh, *wqkvh, *woh, *w1h, *w2h;
    float *attn, *h, *f2;
    cudaGetSymbolAddress((void**)&xh,    g_xh);
    cudaGetSymbolAddress((void**)&qkvh,  g_qkvh);
    cudaGetSymbolAddress((void**)&ctxh,  g_ctxh);
    cudaGetSymbolAddress((void**)&hrh,   g_hrh);
    cudaGetSymbolAddress((void**)&ffh,   g_ffh);
    cudaGetSymbolAddress((void**)&attn,  g_attn);
    cudaGetSymbolAddress((void**)&h,     g_h);
    cudaGetSymbolAddress((void**)&f2,    g_f2);
    cudaGetSymbolAddress((void**)&wqkvh, g_wqkvh);
    cudaGetSymbolAddress((void**)&woh,   g_woh);
    cudaGetSymbolAddress((void**)&w1h,   g_w1h);
    cudaGetSymbolAddress((void**)&w2h,   g_w2h);

    cudaFuncSetAttribute(hgemm<false, false, true>,
                         cudaFuncAttributeMaxDynamicSharedMemorySize, HGEMM_SMEM);
    cudaFuncSetAttribute(hgemm<false, false, false>,
                         cudaFuncAttributeMaxDynamicSharedMemorySize, HGEMM_SMEM);
    cudaFuncSetAttribute(hgemm<true, true, true>,
                         cudaFuncAttributeMaxDynamicSharedMemorySize, HGEMM_SMEM);
    cudaFuncSetAttribute(hgemm<true, false, false>,
                         cudaFuncAttributeMaxDynamicSharedMemorySize, HGEMM_SMEM);
    cudaFuncSetAttribute(flash_attn_h,
                         cudaFuncAttributeMaxDynamicSharedMemorySize, AT_SMEM);

    // ---- prep: everything -> fp16, row-major (streaming only) ----
    {
        const int n_x = NTOK * DMODEL / 4;
        f2h_kernel<<<(n_x + 255) / 256, 256>>>(x, xh, n_x);
        const int n_w = DMODEL * DMODEL / 4;
        const int n_f = DMODEL * DFF / 4;
        f2h_pack_kernel<<<(n_w + 255) / 256, 256>>>(wq, wqkvh, DMODEL, QLD, 0,          n_w);
        f2h_pack_kernel<<<(n_w + 255) / 256, 256>>>(wk, wqkvh, DMODEL, QLD, DMODEL,     n_w);
        f2h_pack_kernel<<<(n_w + 255) / 256, 256>>>(wv, wqkvh, DMODEL, QLD, 2 * DMODEL, n_w);
        f2h_pack_kernel<<<(n_w + 255) / 256, 256>>>(wo, woh, DMODEL, DMODEL, 0, n_w);
        f2h_pack_kernel<<<(n_f + 255) / 256, 256>>>(w1, w1h, DFF,    DFF,    0, n_f);
        f2h_pack_kernel<<<(n_f + 255) / 256, 256>>>(w2, w2h, DMODEL, DMODEL, 0, n_f);
    }

    const dim3 g_qkv(QLD / 128,    NTOK / 128);   // (24, 64)
    const dim3 g_dd (DMODEL / 128, NTOK / 128);   // (8, 64)
    const dim3 g_df (DFF / 128,    NTOK / 128);   // (32, 64)

    // fused QKV projection -> packed fp16 [tok][3072]
    hgemm<false, false, true><<<g_qkv, 256, HGEMM_SMEM>>>(xh, wqkvh, nullptr, qkvh,
                                                          NTOK, QLD, DMODEL);

    // attention -> fp16 ctx
    flash_attn_h<<<dim3(SEQ / 128, NHEAD, BATCH), 256, AT_SMEM>>>(qkvh, ctxh);

    // output projection -> fp32
    hgemm<false, false, false><<<g_dd, 256, HGEMM_SMEM>>>(ctxh, woh, nullptr, attn,
                                                          NTOK, DMODEL, DMODEL);

    // add & norm 1 (h fp32 residual, hrh fp16 for FFN1)
    add_ln_kernel<<<NTOK, 256>>>(x, attn, g1, be1, h, hrh);

    // FFN
    hgemm<true, true,  true ><<<g_df, 256, HGEMM_SMEM>>>(hrh, w1h, b1, ffh, NTOK, DFF,    DMODEL);
    hgemm<true, false, false><<<g_dd, 256, HGEMM_SMEM>>>(ffh, w2h, b2, f2,  NTOK, DMODEL, DFF);

    // add & norm 2
    add_ln_kernel<<<NTOK, 256>>>(h, f2, g2, be2, out, nullptr);
}

// round 9
// speedup vs baseline: 2.6822x; 1.0507x over previous
#include <cuda_runtime.h>
#include <cuda_fp16.h>
#include <math.h>
#include <stdint.h>

// ---------------------------------------------------------------------------
// Problem constants
// ---------------------------------------------------------------------------
#define BATCH   4
#define SEQ     2048
#define DMODEL  1024
#define NHEAD   16
#define DK      64
#define DFF     4096
#define NTOK    (BATCH * SEQ)          // 8192
#define LN_EPS  1e-5f
#define QLD     (3 * DMODEL)           // packed qkv row stride

// ---------------------------------------------------------------------------
// Scratch (device globals — allocation-free rule)
// ---------------------------------------------------------------------------
__device__ __half g_xh   [NTOK * DMODEL];
__device__ __half g_qkvh [NTOK * QLD];
__device__ __half g_ctxh [NTOK * DMODEL];
__device__ __half g_hrh  [NTOK * DMODEL];
__device__ __half g_ffh  [NTOK * DFF];
__device__ float  g_attn [NTOK * DMODEL];
__device__ float  g_h    [NTOK * DMODEL];
__device__ float  g_f2   [NTOK * DMODEL];
// fp16 ROW-MAJOR weights: wh[k][n] = (half)w[k][n]
__device__ __half g_wqkvh[DMODEL * QLD];       // [1024][3072] = wq | wk | wv
__device__ __half g_woh  [DMODEL * DMODEL];
__device__ __half g_w1h  [DMODEL * DFF];
__device__ __half g_w2h  [DFF * DMODEL];

// ---------------------------------------------------------------------------
// Helpers
// ---------------------------------------------------------------------------
__device__ __forceinline__ uint32_t smem_u32(const void* p) {
    return (uint32_t)__cvta_generic_to_shared(p);
}
__device__ __forceinline__ void cp_async16(uint32_t dst, const void* src) {
    asm volatile("cp.async.cg.shared.global [%0], [%1], 16;\n" :: "r"(dst), "l"(src));
}
__device__ __forceinline__ void cp_commit() { asm volatile("cp.async.commit_group;\n"); }
__device__ __forceinline__ void cp_wait1()  { asm volatile("cp.async.wait_group 1;\n"); }
__device__ __forceinline__ void cp_wait0()  { asm volatile("cp.async.wait_group 0;\n"); }

// mma.m16n8k16 row.col f32 += f16 * f16
__device__ __forceinline__ void mma_f16(float* c, const uint32_t* a,
                                        uint32_t b0, uint32_t b1) {
    asm volatile(
        "mma.sync.aligned.m16n8k16.row.col.f32.f16.f16.f32 "
        "{%0,%1,%2,%3}, {%4,%5,%6,%7}, {%8,%9}, {%0,%1,%2,%3};"
        : "+f"(c[0]), "+f"(c[1]), "+f"(c[2]), "+f"(c[3])
        : "r"(a[0]), "r"(a[1]), "r"(a[2]), "r"(a[3]), "r"(b0), "r"(b1));
}

__device__ __forceinline__ void ldsm_x4(uint32_t* r, uint32_t addr) {
    asm volatile("ldmatrix.sync.aligned.m8n8.x4.shared.b16 {%0,%1,%2,%3}, [%4];"
                 : "=r"(r[0]), "=r"(r[1]), "=r"(r[2]), "=r"(r[3]) : "r"(addr));
}
__device__ __forceinline__ void ldsm_x4_trans(uint32_t* r, uint32_t addr) {
    asm volatile("ldmatrix.sync.aligned.m8n8.x4.trans.shared.b16 {%0,%1,%2,%3}, [%4];"
                 : "=r"(r[0]), "=r"(r[1]), "=r"(r[2]), "=r"(r[3]) : "r"(addr));
}

// ---------------------------------------------------------------------------
// Fused prep: one launch converts x + all weights to fp16 (qkv packed).
// Unit = one float4 (4 floats in, 4 halves out).
// ---------------------------------------------------------------------------
#define U_X   (NTOK * DMODEL / 4)          // 2,097,152
#define U_W   (DMODEL * DMODEL / 4)        //   262,144
#define U_F   (DMODEL * DFF / 4)           // 1,048,576
#define U_TOT (U_X + 4 * U_W + 2 * U_F)    // 5,242,880

__device__ __forceinline__ void cv_lin(const float* in, __half* out, int i) {
    float4 v = *(const float4*)(in + 4 * (size_t)i);
    *(__half2*)(out + 4 * (size_t)i)     = __floats2half2_rn(v.x, v.y);
    *(__half2*)(out + 4 * (size_t)i + 2) = __floats2half2_rn(v.z, v.w);
}
__device__ __forceinline__ void cv_pack(const float* in, __half* out, int i, int off) {
    int row = i >> 8, c4 = (i & 255) * 4;          // N = 1024 -> 256 units/row
    float4 v = *(const float4*)(in + (size_t)row * DMODEL + c4);
    __half* o = out + (size_t)row * QLD + off + c4;
    *(__half2*)o       = __floats2half2_rn(v.x, v.y);
    *(__half2*)(o + 2) = __floats2half2_rn(v.z, v.w);
}

__global__ __launch_bounds__(256)
void prep_all_kernel(const float* __restrict__ x,
                     const float* __restrict__ wq, const float* __restrict__ wk,
                     const float* __restrict__ wv, const float* __restrict__ wo,
                     const float* __restrict__ w1, const float* __restrict__ w2,
                     __half* __restrict__ xh, __half* __restrict__ wqkvh,
                     __half* __restrict__ woh, __half* __restrict__ w1h,
                     __half* __restrict__ w2h) {
    int i = blockIdx.x * blockDim.x + threadIdx.x;
    if (i >= U_TOT) return;
    if (i < U_X)            { cv_lin(x, xh, i); return; }
    i -= U_X;
    if (i < U_W)            { cv_pack(wq, wqkvh, i, 0);          return; }
    i -= U_W;
    if (i < U_W)            { cv_pack(wk, wqkvh, i, DMODEL);     return; }
    i -= U_W;
    if (i < U_W)            { cv_pack(wv, wqkvh, i, 2 * DMODEL); return; }
    i -= U_W;
    if (i < U_W)            { cv_lin(wo, woh, i); return; }
    i -= U_W;
    if (i < U_F)            { cv_lin(w1, w1h, i); return; }
    i -= U_F;
    cv_lin(w2, w2h, i);
}

// ---------------------------------------------------------------------------
// FP16 GEMM, ldmatrix fragments, 3-stage cp.async, ONE sync per k-iter.
// C[M,N] = A[M,K] @ B[K,N] (+bias)(+relu). A row-major, B row-major
// (fragments via ldmatrix.trans). 128x128 tile, BK=64, 8 warps.
// ---------------------------------------------------------------------------
#define HLD  72
#define BLD  136
#define HA_H (128 * HLD)
#define HB_H (64 * BLD)
#define HSTAGE_ALL (HA_H + HB_H)
#define HGEMM_SMEM (3 * HSTAGE_ALL * (int)sizeof(__half))

template<bool BIAS, bool RELU, bool HOUT>
__global__ __launch_bounds__(256, 2)
void hgemm(const __half* __restrict__ A, const __half* __restrict__ B,
           const float* __restrict__ bias, void* __restrict__ Cv,
           int M, int N, int K) {
    extern __shared__ __half hsm[];

    const int tid  = threadIdx.x;
    const int lane = tid & 31;
    const int warp = tid >> 5;
    const int wm   = warp & 1;
    const int wn   = warp >> 1;
    const int g    = lane >> 2;
    const int th   = lane & 3;
    const int lrow = lane & 7;
    const int lgrp = lane >> 3;

    const int rowBase = blockIdx.y * 128;
    const int colBase = blockIdx.x * 128;

    float acc[4][4][4];
#pragma unroll
    for (int i = 0; i < 4; i++)
#pragma unroll
        for (int j = 0; j < 4; j++)
#pragma unroll
            for (int r = 0; r < 4; r++) acc[i][j][r] = 0.f;

    uint32_t aoff[4], boff[2];
#pragma unroll
    for (int mt = 0; mt < 4; mt++)
        aoff[mt] = (uint32_t)(((wm * 64 + mt * 16 + (lgrp & 1) * 8 + lrow) * HLD
                               + (lgrp >> 1) * 8) * 2);
#pragma unroll
    for (int p = 0; p < 2; p++)
        boff[p] = (uint32_t)((((lgrp & 1) * 8 + lrow) * BLD
                              + wn * 32 + p * 16 + (lgrp >> 1) * 8) * 2
                             + HA_H * 2);

    auto load_chunk = [&](int c) {
        const int s = c % 3;
        __half* as = hsm + s * HSTAGE_ALL;
        __half* bs = as + HA_H;
        const size_t koff = (size_t)c * 64;
#pragma unroll
        for (int p = 0; p < 4; p++) {
            int idx = tid + p * 256;
            int ra = idx >> 3, ja = (idx & 7) * 8;
            cp_async16(smem_u32(as + ra * HLD + ja),
                       A + (size_t)(rowBase + ra) * K + koff + ja);
            int rb = idx >> 4, jb = (idx & 15) * 8;
            cp_async16(smem_u32(bs + rb * BLD + jb),
                       B + (koff + rb) * N + colBase + jb);
        }
        cp_commit();
    };

    const int nk = K / 64;
    load_chunk(0);
    load_chunk(1);

    for (int it = 0; it < nk; it++) {
        const int s = it % 3;
        if (it + 1 < nk) cp_wait1();     // stage `it` ready; it+1 may fly
        else             cp_wait0();
        __syncthreads();                 // all warps done with stage it-1
        if (it + 2 < nk) load_chunk(it + 2);   // overwrites stage it-1: safe

        const uint32_t sbase = smem_u32(hsm + s * HSTAGE_ALL);
#pragma unroll
        for (int ks = 0; ks < 4; ks++) {
            uint32_t af[4][4], bf[2][4];
#pragma unroll
            for (int mt = 0; mt < 4; mt++)
                ldsm_x4(af[mt], sbase + aoff[mt] + ks * 32);
#pragma unroll
            for (int p = 0; p < 2; p++)
                ldsm_x4_trans(bf[p], sbase + boff[p] + (uint32_t)(ks * 16 * BLD * 2));
#pragma unroll
            for (int mt = 0; mt < 4; mt++) {
                mma_f16(acc[mt][0], af[mt], bf[0][0], bf[0][1]);
                mma_f16(acc[mt][1], af[mt], bf[0][2], bf[0][3]);
                mma_f16(acc[mt][2], af[mt], bf[1][0], bf[1][1]);
                mma_f16(acc[mt][3], af[mt], bf[1][2], bf[1][3]);
            }
        }
    }

    float* Cf = (float*)Cv;
    __half* Ch = (__half*)Cv;
#pragma unroll
    for (int mt = 0; mt < 4; mt++) {
        const int r0 = rowBase + wm * 64 + mt * 16 + g;
#pragma unroll
        for (int nt = 0; nt < 4; nt++) {
            const int c0 = colBase + wn * 32 + nt * 8 + 2 * th;
            float2 v0 = make_float2(acc[mt][nt][0], acc[mt][nt][1]);
            float2 v1 = make_float2(acc[mt][nt][2], acc[mt][nt][3]);
            if (BIAS) {
                float2 bb = *(const float2*)(bias + c0);
                v0.x += bb.x; v0.y += bb.y;
                v1.x += bb.x; v1.y += bb.y;
            }
            if (RELU) {
                v0.x = fmaxf(v0.x, 0.f); v0.y = fmaxf(v0.y, 0.f);
                v1.x = fmaxf(v1.x, 0.f); v1.y = fmaxf(v1.y, 0.f);
            }
            if (HOUT) {
                *(__half2*)(Ch + (size_t)r0 * N + c0)       = __floats2half2_rn(v0.x, v0.y);
                *(__half2*)(Ch + (size_t)(r0 + 8) * N + c0) = __floats2half2_rn(v1.x, v1.y);
            } else {
                *(float2*)(Cf + (size_t)r0 * N + c0)       = v0;
                *(float2*)(Cf + (size_t)(r0 + 8) * N + c0) = v1;
            }
        }
    }
}

// ---------------------------------------------------------------------------
// Flash attention: FP16 mma, P kept in registers (no smem round-trip),
// Q pre-scaled by 1/8 (exact), double-buffered K/V, ONE sync per kv tile.
// Reads packed qkv [tok][3072]: q at +0, k at +1024, v at +2048.
// grid = (SEQ/128, NHEAD, BATCH), 256 threads (8 warps), 16 q-rows per warp.
// smem: K0,V0,K1,V1 = 4 * 64*72 halves = 36,864 B (Q staged in K1/V1 region).
// ---------------------------------------------------------------------------
#define ALD   72
#define ATILE (64 * ALD)
#define AT_SMEM (4 * ATILE * (int)sizeof(__half))

__global__ __launch_bounds__(256)
void flash_attn_h(const __half* __restrict__ qkv, __half* __restrict__ ctx) {
    extern __shared__ __half asm_[];

    const int tid  = threadIdx.x;
    const int lane = tid & 31;
    const int warp = tid >> 5;         // 0..7 -> 16 q rows each
    const int g    = lane >> 2;
    const int th   = lane & 3;
    const int lrow = lane & 7;
    const int lgrp = lane >> 3;
    const int qt   = blockIdx.x;
    const int h    = blockIdx.y;
    const int b    = blockIdx.z;

    const size_t base = (size_t)b * SEQ * QLD + (size_t)h * DK;
    const __half* qp = qkv + base;
    const __half* kp = qkv + base + DMODEL;
    const __half* vp = qkv + base + 2 * DMODEL;

    const int qrow = warp * 16 + g;    // row pair: qrow, qrow+8

    uint32_t koff[4], voff[4];
#pragma unroll
    for (int p = 0; p < 4; p++) {
        koff[p] = (uint32_t)(((p * 16 + (lgrp >> 1) * 8 + lrow) * ALD
                              + (lgrp & 1) * 8) * 2);
        voff[p] = (uint32_t)((((lgrp & 1) * 8 + lrow) * ALD
                              + p * 16 + (lgrp >> 1) * 8) * 2);
    }

    auto load_kv = [&](int kt) {
        __half* kd = asm_ + (kt & 1) * 2 * ATILE;
        __half* vd = kd + ATILE;
#pragma unroll
        for (int i = 0; i < 2; i++) {
            int c = tid + i * 256;              // 0..511
            int r = c >> 3, off = (c & 7) * 8;
            size_t go = (size_t)(kt * 64 + r) * QLD + off;
            cp_async16(smem_u32(kd + r * ALD + off), kp + go);
            cp_async16(smem_u32(vd + r * ALD + off), vp + go);
        }
        cp_commit();
    };
    load_kv(0);                         // -> buffer 0

    // ---- stage Q (pre-scaled by 0.125, exact) into buffer-1 region ----
    __half* Qs = asm_ + 2 * ATILE;      // 128 rows x 72 fits in K1+V1
    const __half2 qsc = __float2half2_rn(0.125f);
    for (int e = tid; e < 128 * 16; e += 256) {
        int r = e >> 4, d4 = (e & 15) * 4;
        uint2 u = *(const uint2*)(qp + (size_t)(qt * 128 + r) * QLD + d4);
        __half2 h0 = __hmul2(*(__half2*)&u.x, qsc);
        __half2 h1 = __hmul2(*(__half2*)&u.y, qsc);
        uint2 w;
        w.x = *(uint32_t*)&h0;
        w.y = *(uint32_t*)&h1;
        *(uint2*)&Qs[r * ALD + d4] = w;
    }
    __syncthreads();

    const uint32_t qoff = (uint32_t)(((warp * 16 + (lgrp & 1) * 8 + lrow) * ALD
                                      + (lgrp >> 1) * 8) * 2);
    uint32_t qf[4][4];
#pragma unroll
    for (int ks = 0; ks < 4; ks++)
        ldsm_x4(qf[ks], smem_u32(Qs) + qoff + ks * 32);

    float m0 = -1e30f, m1 = -1e30f, l0 = 0.f, l1 = 0.f;
    float o[8][4];
#pragma unroll
    for (int i = 0; i < 8; i++)
#pragma unroll
        for (int j = 0; j < 4; j++) o[i][j] = 0.f;

    for (int kt = 0; kt < SEQ / 64; kt++) {
        cp_wait0();                     // KV tile kt landed
        __syncthreads();                // everyone done with buffer kt-1 (and Q ldsm at kt=0)
        if (kt + 1 < SEQ / 64) load_kv(kt + 1);   // overwrites buffer kt-1: safe

        const uint32_t kbase = smem_u32(asm_ + (kt & 1) * 2 * ATILE);
        const uint32_t vbase = kbase + ATILE * 2;   // bytes

        // ---- S = (Q/8) @ K^T ----
        float s[8][4];
#pragma unroll
        for (int nt = 0; nt < 8; nt++)
#pragma unroll
            for (int r = 0; r < 4; r++) s[nt][r] = 0.f;

#pragma unroll
        for (int ks = 0; ks < 4; ks++) {
            const uint32_t k0b = ks * 32;
#pragma unroll
            for (int p = 0; p < 4; p++) {
                uint32_t kf[4];
                ldsm_x4(kf, kbase + koff[p] + k0b);
                mma_f16(s[2 * p],     qf[ks], kf[0], kf[1]);
                mma_f16(s[2 * p + 1], qf[ks], kf[2], kf[3]);
            }
        }

        // ---- online softmax; P packed straight into mma A-fragments ----
        float rm0 = -1e30f, rm1 = -1e30f;
#pragma unroll
        for (int nt = 0; nt < 8; nt++) {
            rm0 = fmaxf(rm0, fmaxf(s[nt][0], s[nt][1]));
            rm1 = fmaxf(rm1, fmaxf(s[nt][2], s[nt][3]));
        }
        rm0 = fmaxf(rm0, __shfl_xor_sync(0xffffffffu, rm0, 1));
        rm0 = fmaxf(rm0, __shfl_xor_sync(0xffffffffu, rm0, 2));
        rm1 = fmaxf(rm1, __shfl_xor_sync(0xffffffffu, rm1, 1));
        rm1 = fmaxf(rm1, __shfl_xor_sync(0xffffffffu, rm1, 2));

        const float mn0 = fmaxf(m0, rm0);
        const float mn1 = fmaxf(m1, rm1);
        const float corr0 = __expf(m0 - mn0);
        const float corr1 = __expf(m1 - mn1);

        uint32_t pf[8][2];              // [nt][0]: rows qrow; [1]: rows qrow+8
        float rs0 = 0.f, rs1 = 0.f;
#pragma unroll
        for (int nt = 0; nt < 8; nt++) {
            float p00 = __expf(s[nt][0] - mn0);
            float p01 = __expf(s[nt][1] - mn0);
            float p10 = __expf(s[nt][2] - mn1);
            float p11 = __expf(s[nt][3] - mn1);
            rs0 += p00 + p01;
            rs1 += p10 + p11;
            __half2 h0 = __floats2half2_rn(p00, p01);
            __half2 h1 = __floats2half2_rn(p10, p11);
            pf[nt][0] = *(uint32_t*)&h0;
            pf[nt][1] = *(uint32_t*)&h1;
        }
        rs0 += __shfl_xor_sync(0xffffffffu, rs0, 1);
        rs0 += __shfl_xor_sync(0xffffffffu, rs0, 2);
        rs1 += __shfl_xor_sync(0xffffffffu, rs1, 1);
        rs1 += __shfl_xor_sync(0xffffffffu, rs1, 2);

        l0 = l0 * corr0 + rs0;
        l1 = l1 * corr1 + rs1;
        m0 = mn0;
        m1 = mn1;

#pragma unroll
        for (int dt = 0; dt < 8; dt++) {
            o[dt][0] *= corr0; o[dt][1] *= corr0;
            o[dt][2] *= corr1; o[dt][3] *= corr1;
        }

        // ---- O += P @ V (A-frags from registers; V via ldmatrix.trans) ----
#pragma unroll
        for (int ks = 0; ks < 4; ks++) {
            uint32_t af[4];
            af[0] = pf[2 * ks][0];
            af[1] = pf[2 * ks][1];
            af[2] = pf[2 * ks + 1][0];
            af[3] = pf[2 * ks + 1][1];
            const uint32_t kvb = (uint32_t)(ks * 16 * ALD * 2);
#pragma unroll
            for (int p = 0; p < 4; p++) {
                uint32_t vf[4];
                ldsm_x4_trans(vf, vbase + voff[p] + kvb);
                mma_f16(o[2 * p],     af, vf[0], vf[1]);
                mma_f16(o[2 * p + 1], af, vf[2], vf[3]);
            }
        }
    }

    // epilogue -> fp16 ctx (stride DMODEL)
    const float inv0 = 1.0f / l0;
    const float inv1 = 1.0f / l1;
    const size_t cbase = (size_t)b * SEQ * DMODEL + (size_t)h * DK;
    const size_t row0 = cbase + (size_t)(qt * 128 + qrow) * DMODEL;
    const size_t row1 = cbase + (size_t)(qt * 128 + qrow + 8) * DMODEL;
#pragma unroll
    for (int dt = 0; dt < 8; dt++) {
        const int c0 = dt * 8 + 2 * th;
        *(__half2*)(ctx + row0 + c0) = __floats2half2_rn(o[dt][0] * inv0, o[dt][1] * inv0);
        *(__half2*)(ctx + row1 + c0) = __floats2half2_rn(o[dt][2] * inv1, o[dt][3] * inv1);
    }
}

// ---------------------------------------------------------------------------
// out = LayerNorm(a + b) * gamma + beta; optional fp16 copy for next GEMM.
// ---------------------------------------------------------------------------
__global__ __launch_bounds__(256)
void add_ln_kernel(const float* __restrict__ a, const float* __restrict__ b,
                   const float* __restrict__ gamma, const float* __restrict__ beta,
                   float* __restrict__ out, __half* __restrict__ out_h) {
    const int row = blockIdx.x;
    const int tid = threadIdx.x;
    const size_t off = (size_t)row * DMODEL;

    __shared__ float r1[8], r2[8];

    float vals[4];
    float sum = 0.f, sq = 0.f;
#pragma unroll
    for (int t = 0; t < 4; t++) {
        int c = tid + t * 256;
        float vv = a[off + c] + b[off + c];
        vals[t] = vv;
        sum += vv;
        sq  += vv * vv;
    }
#pragma unroll
    for (int o = 16; o > 0; o >>= 1) {
        sum += __shfl_xor_sync(0xffffffffu, sum, o);
        sq  += __shfl_xor_sync(0xffffffffu, sq,  o);
    }
    const int wid = tid >> 5;
    if ((tid & 31) == 0) { r1[wid] = sum; r2[wid] = sq; }
    __syncthreads();
    float tot1 = 0.f, tot2 = 0.f;
#pragma unroll
    for (int w = 0; w < 8; w++) { tot1 += r1[w]; tot2 += r2[w]; }

    const float mu   = tot1 * (1.0f / DMODEL);
    const float var  = tot2 * (1.0f / DMODEL) - mu * mu;
    const float rstd = rsqrtf(var + LN_EPS);

#pragma unroll
    for (int t = 0; t < 4; t++) {
        int c = tid + t * 256;
        float y = (vals[t] - mu) * rstd * gamma[c] + beta[c];
        out[off + c] = y;
        if (out_h) out_h[off + c] = __float2half(y);
    }
}

// ---------------------------------------------------------------------------
// Launcher
// ---------------------------------------------------------------------------
extern "C" void kernel_launch(void* const* d_in, const int* in_sizes, int n_in,
                              void* d_out, int out_size) {
    (void)in_sizes; (void)n_in; (void)out_size;
    const float* x   = (const float*)d_in[0];
    const float* wq  = (const float*)d_in[1];
    const float* wk  = (const float*)d_in[2];
    const float* wv  = (const float*)d_in[3];
    const float* wo  = (const float*)d_in[4];
    const float* w1  = (const float*)d_in[5];
    const float* b1  = (const float*)d_in[6];
    const float* w2  = (const float*)d_in[7];
    const float* b2  = (const float*)d_in[8];
    const float* g1  = (const float*)d_in[9];
    const float* be1 = (const float*)d_in[10];
    const float* g2  = (const float*)d_in[11];
    const float* be2 = (const float*)d_in[12];
    float* out = (float*)d_out;

    __half *xh, *qkvh, *ctxh, *hrh, *ffh, *wqkvh, *woh, *w1h, *w2h;
    float *attn, *h, *f2;
    cudaGetSymbolAddress((void**)&xh,    g_xh);
    cudaGetSymbolAddress((void**)&qkvh,  g_qkvh);
    cudaGetSymbolAddress((void**)&ctxh,  g_ctxh);
    cudaGetSymbolAddress((void**)&hrh,   g_hrh);
    cudaGetSymbolAddress((void**)&ffh,   g_ffh);
    cudaGetSymbolAddress((void**)&attn,  g_attn);
    cudaGetSymbolAddress((void**)&h,     g_h);
    cudaGetSymbolAddress((void**)&f2,    g_f2);
    cudaGetSymbolAddress((void**)&wqkvh, g_wqkvh);
    cudaGetSymbolAddress((void**)&woh,   g_woh);
    cudaGetSymbolAddress((void**)&w1h,   g_w1h);
    cudaGetSymbolAddress((void**)&w2h,   g_w2h);

    cudaFuncSetAttribute(hgemm<false, false, true>,
                         cudaFuncAttributeMaxDynamicSharedMemorySize, HGEMM_SMEM);
    cudaFuncSetAttribute(hgemm<false, false, false>,
                         cudaFuncAttributeMaxDynamicSharedMemorySize, HGEMM_SMEM);
    cudaFuncSetAttribute(hgemm<true, true, true>,
                         cudaFuncAttributeMaxDynamicSharedMemorySize, HGEMM_SMEM);
    cudaFuncSetAttribute(hgemm<true, false, false>,
                         cudaFuncAttributeMaxDynamicSharedMemorySize, HGEMM_SMEM);
    cudaFuncSetAttribute(flash_attn_h,
                         cudaFuncAttributeMaxDynamicSharedMemorySize, AT_SMEM);

    // ---- fused prep: one launch converts everything to fp16 ----
    prep_all_kernel<<<(U_TOT + 255) / 256, 256>>>(x, wq, wk, wv, wo, w1, w2,
                                                  xh, wqkvh, woh, w1h, w2h);

    const dim3 g_qkv(QLD / 128,    NTOK / 128);   // (24, 64)
    const dim3 g_dd (DMODEL / 128, NTOK / 128);   // (8, 64)
    const dim3 g_df (DFF / 128,    NTOK / 128);   // (32, 64)

    // fused QKV projection -> packed fp16 [tok][3072]
    hgemm<false, false, true><<<g_qkv, 256, HGEMM_SMEM>>>(xh, wqkvh, nullptr, qkvh,
                                                          NTOK, QLD, DMODEL);

    // attention -> fp16 ctx
    flash_attn_h<<<dim3(SEQ / 128, NHEAD, BATCH), 256, AT_SMEM>>>(qkvh, ctxh);

    // output projection -> fp32
    hgemm<false, false, false><<<g_dd, 256, HGEMM_SMEM>>>(ctxh, woh, nullptr, attn,
                                                          NTOK, DMODEL, DMODEL);

    // add & norm 1 (h fp32 residual, hrh fp16 for FFN1)
    add_ln_kernel<<<NTOK, 256>>>(x, attn, g1, be1, h, hrh);

    // FFN
    hgemm<true, true,  true ><<<g_df, 256, HGEMM_SMEM>>>(hrh, w1h, b1, ffh, NTOK, DFF,    DMODEL);
    hgemm<true, false, false><<<g_dd, 256, HGEMM_SMEM>>>(ffh, w2h, b2, f2,  NTOK, DMODEL, DFF);

    // add & norm 2
    add_ln_kernel<<<NTOK, 256>>>(h, f2, g2, be2, out, nullptr);
}